// round 6
// baseline (speedup 1.0000x reference)
#include <cuda_runtime.h>
#include <cuda_bf16.h>
#include <math.h>
#include <stdint.h>

#define NN 50000
#define NE 800000
#define DH 128
#define DO 47
#define MM (2*NN)
#define OPB (NN*(DH+DO+DO))
#define NB_SCAN ((NN + 1023)/1024)

// ---------------- scratch ----------------
__device__ float g_x2[MM*DH];
__device__ float g_t [MM*DH];
__device__ float g_r [MM*DH];
__device__ float g_h [MM*DH];
__device__ float g_t2[MM*DO];
__device__ float g_r2[MM*DO];
__device__ int   g_deg[NN];
__device__ int   g_off[NN+1];
__device__ int   g_pos[NN];
__device__ int   g_csr[NE];
__device__ int   g_bsum[64];
__device__ __align__(16) uint8_t g_wimg[2*65536 + 2*65536 + 2*32768];

// ---------------- helpers ----------------
__device__ __forceinline__ uint32_t smem_u32(const void* p) {
    uint32_t a;
    asm("{ .reg .u64 t; cvta.to.shared.u64 t, %1; cvt.u32.u64 %0, t; }" : "=r"(a) : "l"(p));
    return a;
}
__device__ __forceinline__ void ldsm4(uint32_t* r, uint32_t addr) {
    asm volatile("ldmatrix.sync.aligned.m8n8.x4.shared.b16 {%0,%1,%2,%3}, [%4];"
        : "=r"(r[0]), "=r"(r[1]), "=r"(r[2]), "=r"(r[3]) : "r"(addr));
}
__device__ __forceinline__ void mma16816(float* c, const uint32_t* a, uint32_t b0, uint32_t b1) {
    asm volatile("mma.sync.aligned.m16n8k16.row.col.f32.bf16.bf16.f32 "
        "{%0,%1,%2,%3}, {%4,%5,%6,%7}, {%8,%9}, {%0,%1,%2,%3};"
        : "+f"(c[0]), "+f"(c[1]), "+f"(c[2]), "+f"(c[3])
        : "r"(a[0]), "r"(a[1]), "r"(a[2]), "r"(a[3]), "r"(b0), "r"(b1));
}
__device__ __forceinline__ void cvt_hilo(const float* v, uint32_t* hp, uint32_t* lp) {
    #pragma unroll
    for (int p = 0; p < 4; p++) {
        __nv_bfloat162 h2 = __floats2bfloat162_rn(v[2*p], v[2*p+1]);
        float l0 = v[2*p]   - __low2float(h2);
        float l1 = v[2*p+1] - __high2float(h2);
        __nv_bfloat162 l2 = __floats2bfloat162_rn(l0, l1);
        hp[p] = *(uint32_t*)&h2;
        lp[p] = *(uint32_t*)&l2;
    }
}

// ---------------- weight image writer (shared with prep kernel) ----------------
__device__ __forceinline__ void wconv_item(int id,
        const float* Wl0, const float* Wr0, const float* Wl1, const float* Wr1,
        const float* Wl2, const float* Wr2) {
    const float* src = nullptr;
    uint8_t *imgHi, *imgLo;
    int row, c8;
    if (id < 4096) {
        row = id >> 4; c8 = id & 15;
        imgHi = g_wimg;          imgLo = g_wimg + 65536;
        src = (row < 128) ? (Wl0 + (size_t)row*128) : (Wr0 + (size_t)(row-128)*128);
    } else if (id < 8192) {
        id -= 4096; row = id >> 4; c8 = id & 15;
        imgHi = g_wimg + 131072; imgLo = g_wimg + 196608;
        src = (row < 128) ? (Wl1 + (size_t)row*128) : (Wr1 + (size_t)(row-128)*128);
    } else if (id < 10240) {
        id -= 8192; row = id >> 4; c8 = id & 15;
        imgHi = g_wimg + 262144; imgLo = g_wimg + 294912;
        if (row < 47)                     src = Wl2 + (size_t)row*128;
        else if (row >= 64 && row < 111)  src = Wr2 + (size_t)(row-64)*128;
        else                              src = nullptr;
    } else return;
    float v[8];
    #pragma unroll
    for (int j = 0; j < 8; j++) v[j] = src ? src[c8*8 + j] : 0.f;
    uint32_t hp[4], lp[4];
    cvt_hilo(v, hp, lp);
    uint32_t off = (uint32_t)row*256u + (uint32_t)((c8 ^ (row & 7)) << 4);
    *(uint4*)(imgHi + off) = make_uint4(hp[0], hp[1], hp[2], hp[3]);
    *(uint4*)(imgLo + off) = make_uint4(lp[0], lp[1], lp[2], lp[3]);
}

// ---------------- prep: noise branch + weight conversion fused ----------------
#define NOISE_BLOCKS (NN/8)   /* 6250 blocks x 8 warps x 1 node */
__global__ void k_prep(const float* __restrict__ x, const float* __restrict__ noise,
                       const float* Wl0, const float* Wr0,
                       const float* Wl1, const float* Wr1,
                       const float* Wl2, const float* Wr2) {
    if (blockIdx.x < NOISE_BLOCKS) {
        int w = (blockIdx.x*blockDim.x + threadIdx.x) >> 5;
        int lane = threadIdx.x & 31;
        const float4 nv = *(const float4*)(noise + (size_t)w*DH + lane*4);
        float ss = nv.x*nv.x + nv.y*nv.y + nv.z*nv.z + nv.w*nv.w;
        #pragma unroll
        for (int o = 16; o; o >>= 1) ss += __shfl_xor_sync(0xffffffffu, ss, o);
        float sc = 0.1f / fmaxf(sqrtf(ss), 1e-12f);
        float4 xv = *(const float4*)(x + (size_t)w*DH + lane*4);
        float4 xn;
        xn.x = xv.x + ((xv.x>0.f)?1.f:((xv.x<0.f)?-1.f:0.f)) * nv.x * sc;
        xn.y = xv.y + ((xv.y>0.f)?1.f:((xv.y<0.f)?-1.f:0.f)) * nv.y * sc;
        xn.z = xv.z + ((xv.z>0.f)?1.f:((xv.z<0.f)?-1.f:0.f)) * nv.z * sc;
        xn.w = xv.w + ((xv.w>0.f)?1.f:((xv.w<0.f)?-1.f:0.f)) * nv.w * sc;
        *(float4*)(g_x2 + (size_t)w*DH      + lane*4) = xv;
        *(float4*)(g_x2 + (size_t)(NN+w)*DH + lane*4) = xn;
    } else {
        int id = (blockIdx.x - NOISE_BLOCKS)*blockDim.x + threadIdx.x;
        wconv_item(id, Wl0, Wr0, Wl1, Wr1, Wl2, Wr2);
    }
}

// ---------------- CSR build ----------------
__global__ void k_zero() {
    int i = blockIdx.x*blockDim.x + threadIdx.x;
    if (i < NN) g_deg[i] = 0;
    if (i < 64) g_bsum[i] = 0;
}
__global__ void k_hist(const int* __restrict__ ei) {
    int e = blockIdx.x*blockDim.x + threadIdx.x;
    if (e < NE) atomicAdd(&g_deg[ei[NE + e]], 1);
}
__global__ void k_scan1() {
    __shared__ int ws[32];
    int tid = threadIdx.x, lane = tid & 31, w = tid >> 5;
    int gid = blockIdx.x*1024 + tid;
    int s = (gid < NN) ? g_deg[gid] : 0;
    #pragma unroll
    for (int o = 1; o < 32; o <<= 1) {
        int t = __shfl_up_sync(0xffffffffu, s, o);
        if (lane >= o) s += t;
    }
    if (lane == 31) ws[w] = s;
    __syncthreads();
    if (w == 0) {
        int x = ws[lane];
        #pragma unroll
        for (int o = 1; o < 32; o <<= 1) {
            int t = __shfl_up_sync(0xffffffffu, x, o);
            if (lane >= o) x += t;
        }
        ws[lane] = x;
    }
    __syncthreads();
    if (w > 0) s += ws[w-1];
    if (gid < NN) g_off[gid+1] = s;
    if (tid == 1023) g_bsum[blockIdx.x] = s;
}
__global__ void k_scan2() {
    __shared__ int s[64];
    int tid = threadIdx.x;
    int v = g_bsum[tid];
    s[tid] = v; __syncthreads();
    for (int o = 1; o < 64; o <<= 1) {
        int t = (tid >= o) ? s[tid-o] : 0;
        __syncthreads(); s[tid] += t; __syncthreads();
    }
    g_bsum[tid] = s[tid] - v;
}
__global__ void k_scan3() {
    int gid = blockIdx.x*1024 + threadIdx.x;
    if (gid >= NN) return;
    int incl = g_off[gid+1] + g_bsum[blockIdx.x];
    g_off[gid+1] = incl;
    g_pos[gid]   = incl - g_deg[gid];
    if (gid == 0) g_off[0] = 0;
}
__global__ void k_fill(const int* __restrict__ ei) {
    int e = blockIdx.x*blockDim.x + threadIdx.x;
    if (e < NE) {
        int dst = ei[NE + e];
        int p = atomicAdd(&g_pos[dst], 1);
        g_csr[p] = ei[e];
    }
}

// ---------------- merged N=256 bf16-split GEMM (512 threads, 16 warps) ----------------
// smem: Ah[0,32K) Al[32K,64K) Bh[64K,128K) Bl[128K,192K)
// C[M,256] = X[M,128] @ [Wl;Wr]^T; cols<128 -> tOut (stride 128), cols>=128 -> rOut.
__global__ void __launch_bounds__(512) k_gemm256(
    const float* __restrict__ X,
    const uint8_t* __restrict__ imgHi, const uint8_t* __restrict__ imgLo,
    float* __restrict__ tOut, float* __restrict__ rOut, int M)
{
    extern __shared__ char smem[];
    const int tid = threadIdx.x;
    const int bm = blockIdx.x * 128;
    uint32_t sb = smem_u32(smem);

    // A fill: 2048 items, 4 per thread
    #pragma unroll
    for (int i = 0; i < 4; i++) {
        int id = tid + i*512;
        int row = id >> 4, c8 = id & 15;
        int gm = bm + row;
        float v[8];
        if (gm < M) {
            float4 f0 = *(const float4*)(X + (size_t)gm*128 + c8*8);
            float4 f1 = *(const float4*)(X + (size_t)gm*128 + c8*8 + 4);
            v[0]=f0.x; v[1]=f0.y; v[2]=f0.z; v[3]=f0.w;
            v[4]=f1.x; v[5]=f1.y; v[6]=f1.z; v[7]=f1.w;
        } else {
            #pragma unroll
            for (int j = 0; j < 8; j++) v[j] = 0.f;
        }
        uint32_t hp[4], lp[4];
        cvt_hilo(v, hp, lp);
        uint32_t off = (uint32_t)row*256u + (uint32_t)((c8 ^ (row & 7)) << 4);
        *(uint4*)(smem + off)         = make_uint4(hp[0], hp[1], hp[2], hp[3]);
        *(uint4*)(smem + 32768 + off) = make_uint4(lp[0], lp[1], lp[2], lp[3]);
    }
    // B copy: 64KB hi + 64KB lo
    {
        const uint4* bh = (const uint4*)imgHi;
        const uint4* bl = (const uint4*)imgLo;
        #pragma unroll
        for (int i = 0; i < 8; i++) {
            int id = tid + i*512;
            ((uint4*)(smem +  65536))[id] = bh[id];
            ((uint4*)(smem + 131072))[id] = bl[id];
        }
    }
    __syncthreads();

    const int lane = tid & 31, w = tid >> 5;
    const int tm = (w >> 2) * 32, tn = (w & 3) * 64;
    const int lrow = lane & 15, lsel = lane >> 4;

    float acc[2][8][4];
    #pragma unroll
    for (int a = 0; a < 2; a++)
        #pragma unroll
        for (int b = 0; b < 8; b++)
            #pragma unroll
            for (int c = 0; c < 4; c++) acc[a][b][c] = 0.f;

    #pragma unroll
    for (int term = 0; term < 3; term++) {
        uint32_t abase = sb + (term == 2 ? 32768u : 0u);
        uint32_t bbase = sb + 65536u + (term == 1 ? 65536u : 0u);
        #pragma unroll
        for (int k16 = 0; k16 < 8; k16++) {
            const int c8 = k16*2 + lsel;
            uint32_t a[2][4];
            #pragma unroll
            for (int mt = 0; mt < 2; mt++) {
                int row = tm + mt*16 + lrow;
                ldsm4(a[mt], abase + (uint32_t)row*256u + (uint32_t)((c8 ^ (row & 7)) << 4));
            }
            uint32_t b[4][4];
            #pragma unroll
            for (int bt = 0; bt < 4; bt++) {
                int n = tn + bt*16 + lrow;
                ldsm4(b[bt], bbase + (uint32_t)n*256u + (uint32_t)((c8 ^ (n & 7)) << 4));
            }
            #pragma unroll
            for (int mt = 0; mt < 2; mt++)
                #pragma unroll
                for (int bt = 0; bt < 4; bt++) {
                    mma16816(acc[mt][bt*2+0], a[mt], b[bt][0], b[bt][2]);
                    mma16816(acc[mt][bt*2+1], a[mt], b[bt][1], b[bt][3]);
                }
        }
    }

    // epilogue: cols<128 -> tOut, else rOut (both fp32, stride 128)
    float* dst = (tn < 128) ? tOut : rOut;
    const int cbase = tn & 127;
    #pragma unroll
    for (int mt = 0; mt < 2; mt++) {
        int r0 = bm + tm + mt*16 + (lane >> 2);
        int r1 = r0 + 8;
        #pragma unroll
        for (int nt = 0; nt < 8; nt++) {
            int col = cbase + nt*8 + (lane & 3)*2;
            if (r0 < M) *(float2*)(dst + (size_t)r0*128 + col)
                = make_float2(acc[mt][nt][0], acc[mt][nt][1]);
            if (r1 < M) *(float2*)(dst + (size_t)r1*128 + col)
                = make_float2(acc[mt][nt][2], acc[mt][nt][3]);
        }
    }
}

// ---------------- layer-2 GEMM (N=128 image: [Wl2|0|Wr2|0]), 256 threads ----------------
__global__ void __launch_bounds__(256) k_gemm47(
    const float* __restrict__ X0, const float* __restrict__ X1, int NSPLIT,
    const uint8_t* __restrict__ imgHi, const uint8_t* __restrict__ imgLo,
    float* __restrict__ out0, float* __restrict__ out1, int M)
{
    extern __shared__ char smem[];
    const int tid = threadIdx.x;
    const int bm = blockIdx.x * 128;
    uint32_t sb = smem_u32(smem);

    #pragma unroll
    for (int i = 0; i < 8; i++) {
        int id = tid + i*256;
        int row = id >> 4, c8 = id & 15;
        int gm = bm + row;
        float v[8];
        if (gm < M) {
            const float* src = (gm < NSPLIT) ? (X0 + (size_t)gm*128)
                                             : (X1 + (size_t)(gm - NSPLIT)*128);
            float4 f0 = *(const float4*)(src + c8*8);
            float4 f1 = *(const float4*)(src + c8*8 + 4);
            v[0]=f0.x; v[1]=f0.y; v[2]=f0.z; v[3]=f0.w;
            v[4]=f1.x; v[5]=f1.y; v[6]=f1.z; v[7]=f1.w;
        } else {
            #pragma unroll
            for (int j = 0; j < 8; j++) v[j] = 0.f;
        }
        uint32_t hp[4], lp[4];
        cvt_hilo(v, hp, lp);
        uint32_t off = (uint32_t)row*256u + (uint32_t)((c8 ^ (row & 7)) << 4);
        *(uint4*)(smem + off)         = make_uint4(hp[0], hp[1], hp[2], hp[3]);
        *(uint4*)(smem + 32768 + off) = make_uint4(lp[0], lp[1], lp[2], lp[3]);
    }
    {
        const uint4* bh = (const uint4*)imgHi;
        const uint4* bl = (const uint4*)imgLo;
        #pragma unroll
        for (int i = 0; i < 8; i++) {
            int id = tid + i*256;
            ((uint4*)(smem + 65536))[id] = bh[id];
            ((uint4*)(smem + 98304))[id] = bl[id];
        }
    }
    __syncthreads();

    const int lane = tid & 31, w = tid >> 5;
    const int tm = (w >> 1) * 32, tn = (w & 1) * 64;
    const int lrow = lane & 15, lsel = lane >> 4;

    float acc[2][8][4];
    #pragma unroll
    for (int a = 0; a < 2; a++)
        #pragma unroll
        for (int b = 0; b < 8; b++)
            #pragma unroll
            for (int c = 0; c < 4; c++) acc[a][b][c] = 0.f;

    #pragma unroll
    for (int term = 0; term < 3; term++) {
        uint32_t abase = sb + (term == 2 ? 32768u : 0u);
        uint32_t bbase = sb + (term == 1 ? 98304u : 65536u);
        #pragma unroll
        for (int k16 = 0; k16 < 8; k16++) {
            const int c8 = k16*2 + lsel;
            uint32_t a[2][4];
            #pragma unroll
            for (int mt = 0; mt < 2; mt++) {
                int row = tm + mt*16 + lrow;
                ldsm4(a[mt], abase + (uint32_t)row*256u + (uint32_t)((c8 ^ (row & 7)) << 4));
            }
            uint32_t b[4][4];
            #pragma unroll
            for (int bt = 0; bt < 4; bt++) {
                int n = tn + bt*16 + lrow;
                ldsm4(b[bt], bbase + (uint32_t)n*256u + (uint32_t)((c8 ^ (n & 7)) << 4));
            }
            #pragma unroll
            for (int mt = 0; mt < 2; mt++)
                #pragma unroll
                for (int bt = 0; bt < 4; bt++) {
                    mma16816(acc[mt][bt*2+0], a[mt], b[bt][0], b[bt][2]);
                    mma16816(acc[mt][bt*2+1], a[mt], b[bt][1], b[bt][3]);
                }
        }
    }

    float* dst = (w & 1) ? out1 : out0;   // cols 0-63 -> t2, 64-127 -> r2
    #pragma unroll
    for (int mt = 0; mt < 2; mt++) {
        int r0 = bm + tm + mt*16 + (lane >> 2);
        int r1 = r0 + 8;
        #pragma unroll
        for (int nt = 0; nt < 8; nt++) {
            int cl = nt*8 + (lane & 3)*2;
            if (cl < DO) {
                if (r0 < M) dst[(size_t)r0*DO + cl] = acc[mt][nt][0];
                if (r1 < M) dst[(size_t)r1*DO + cl] = acc[mt][nt][2];
            }
            if (cl + 1 < DO) {
                if (r0 < M) dst[(size_t)r0*DO + cl + 1] = acc[mt][nt][1];
                if (r1 < M) dst[(size_t)r1*DO + cl + 1] = acc[mt][nt][3];
            }
        }
    }
}

// ---------------- 128-dim mean-agg + bias + self + relu (fp32) ----------------
__global__ void k_agg128(const float* __restrict__ t, const float* __restrict__ r,
                         const float* __restrict__ bias,
                         float* __restrict__ hout, float* __restrict__ dout)
{
    int w = (blockIdx.x*blockDim.x + threadIdx.x) >> 5;
    int lane = threadIdx.x & 31;
    if (w >= MM) return;
    int b = (w >= NN);
    int i = w - b*NN;
    int base = b*NN;
    int e0 = g_off[i], e1 = g_off[i+1];
    float4 acc = make_float4(0.f,0.f,0.f,0.f);
    for (int e = e0; e < e1; e++) {
        int j = g_csr[e];
        float4 v = *(const float4*)(t + ((size_t)(base + j) << 7) + (lane << 2));
        acc.x += v.x; acc.y += v.y; acc.z += v.z; acc.w += v.w;
    }
    float inv = (e1 > e0) ? 1.f/(float)(e1 - e0) : 0.f;
    float4 bb = *(const float4*)(bias + (lane << 2));
    float4 rr = *(const float4*)(r + ((size_t)w << 7) + (lane << 2));
    float4 o;
    o.x = fmaxf(fmaf(acc.x, inv, bb.x + rr.x), 0.f);
    o.y = fmaxf(fmaf(acc.y, inv, bb.y + rr.y), 0.f);
    o.z = fmaxf(fmaf(acc.z, inv, bb.z + rr.z), 0.f);
    o.w = fmaxf(fmaf(acc.w, inv, bb.w + rr.w), 0.f);
    if (hout) *(float4*)(hout + ((size_t)w << 7) + (lane << 2)) = o;
    if (dout) *(float4*)(dout + (size_t)b*OPB + (size_t)i*DH + (lane << 2)) = o;
}

// ---------------- 47-dim agg + bias + self, z and log_softmax(y) ----------------
__global__ void k_agg47(const float* __restrict__ t2, const float* __restrict__ r2,
                        const float* __restrict__ bias, float* __restrict__ dout)
{
    int w = (blockIdx.x*blockDim.x + threadIdx.x) >> 5;
    int lane = threadIdx.x & 31;
    if (w >= MM) return;
    int b = (w >= NN);
    int i = w - b*NN;
    int base = b*NN;
    int f0 = lane*2, f1 = lane*2 + 1;
    bool v0 = (f0 < DO), v1 = (f1 < DO);
    int e0 = g_off[i], e1 = g_off[i+1];
    float a0 = 0.f, a1 = 0.f;
    for (int e = e0; e < e1; e++) {
        const float* row = t2 + (size_t)(base + g_csr[e]) * DO;
        if (v0) a0 += row[f0];
        if (v1) a1 += row[f1];
    }
    float inv = (e1 > e0) ? 1.f/(float)(e1 - e0) : 0.f;
    float z0 = v0 ? fmaf(a0, inv, bias[f0] + r2[(size_t)w*DO + f0]) : -INFINITY;
    float z1 = v1 ? fmaf(a1, inv, bias[f1] + r2[(size_t)w*DO + f1]) : -INFINITY;
    float m = fmaxf(z0, z1);
    #pragma unroll
    for (int o = 16; o; o >>= 1) m = fmaxf(m, __shfl_xor_sync(0xffffffffu, m, o));
    float s = (v0 ? expf(z0 - m) : 0.f) + (v1 ? expf(z1 - m) : 0.f);
    #pragma unroll
    for (int o = 16; o; o >>= 1) s += __shfl_xor_sync(0xffffffffu, s, o);
    float lse = m + logf(s);
    float* ybase = dout + (size_t)b*OPB + (size_t)NN*DH        + (size_t)i*DO;
    float* zbase = dout + (size_t)b*OPB + (size_t)NN*(DH + DO) + (size_t)i*DO;
    if (v0) { zbase[f0] = z0; ybase[f0] = z0 - lse; }
    if (v1) { zbase[f1] = z1; ybase[f1] = z1 - lse; }
}

// ---------------- orchestration ----------------
extern "C" void kernel_launch(void* const* d_in, const int* in_sizes, int n_in,
                              void* d_out, int out_size)
{
    const float* x     = (const float*)d_in[0];
    const int*   ei    = (const int*)  d_in[1];
    const float* noise = (const float*)d_in[2];
    const float* Wl0   = (const float*)d_in[3];
    const float* bl0   = (const float*)d_in[4];
    const float* Wr0   = (const float*)d_in[5];
    const float* Wl1   = (const float*)d_in[6];
    const float* bl1   = (const float*)d_in[7];
    const float* Wr1   = (const float*)d_in[8];
    const float* Wl2   = (const float*)d_in[9];
    const float* bl2   = (const float*)d_in[10];
    const float* Wr2   = (const float*)d_in[11];
    float* out = (float*)d_out;

    float *px2, *pt, *pr, *ph, *pt2, *pr2;
    uint8_t* pw;
    cudaGetSymbolAddress((void**)&px2, g_x2);
    cudaGetSymbolAddress((void**)&pt,  g_t);
    cudaGetSymbolAddress((void**)&pr,  g_r);
    cudaGetSymbolAddress((void**)&ph,  g_h);
    cudaGetSymbolAddress((void**)&pt2, g_t2);
    cudaGetSymbolAddress((void**)&pr2, g_r2);
    cudaGetSymbolAddress((void**)&pw,  g_wimg);

    const int SM256 = 196608;   // 192KB
    const int SM47  = 131072;   // 128KB
    cudaFuncSetAttribute(k_gemm256, cudaFuncAttributeMaxDynamicSharedMemorySize, SM256);
    cudaFuncSetAttribute(k_gemm47,  cudaFuncAttributeMaxDynamicSharedMemorySize, SM47);

    int gBlocks = (MM + 127)/128;        // 782
    int aggBlocks = (MM*32 + 255)/256;

    // idx 0: noise + weight conversion (fused)
    k_prep<<<NOISE_BLOCKS + 40, 256>>>(x, noise, Wl0, Wr0, Wl1, Wr1, Wl2, Wr2);
    // idx 1-2: degree histogram
    k_zero <<<(NN + 255)/256, 256>>>();
    k_hist <<<(NE + 255)/256, 256>>>(ei);
    // idx 3: layer-0 GEMM (ncu capture lands here)
    k_gemm256<<<gBlocks, 512, SM256>>>(px2, pw, pw + 65536, pt, pr, MM);
    // idx 4-7: finish CSR
    k_scan1<<<NB_SCAN, 1024>>>();
    k_scan2<<<1, 64>>>();
    k_scan3<<<NB_SCAN, 1024>>>();
    k_fill <<<(NE + 255)/256, 256>>>(ei);
    // layer 0 agg -> h1
    k_agg128<<<aggBlocks, 256>>>(pt, pr, bl0, ph, nullptr);
    // layer 1
    k_gemm256<<<gBlocks, 512, SM256>>>(ph, pw + 131072, pw + 196608, pt, pr, MM);
    k_agg128<<<aggBlocks, 256>>>(pt, pr, bl1, nullptr, out);
    // layer 2 (reads h2 from d_out)
    k_gemm47<<<gBlocks, 256, SM47>>>(out, out + OPB, NN,
                                     pw + 262144, pw + 294912, pt2, pr2, MM);
    k_agg47<<<aggBlocks, 256>>>(pt2, pr2, bl2, out);
}

// round 7
// speedup vs baseline: 1.0190x; 1.0190x over previous
#include <cuda_runtime.h>
#include <cuda_bf16.h>
#include <math.h>
#include <stdint.h>

#define NN 50000
#define NE 800000
#define DH 128
#define DO 47
#define MM (2*NN)
#define OPB (NN*(DH+DO+DO))
#define NB_SCAN ((NN + 1023)/1024)

// ---------------- scratch ----------------
__device__ float g_x2[MM*DH];
__device__ float g_t [MM*DH];
__device__ float g_r [MM*DH];
__device__ float g_h [MM*DH];
__device__ float g_t2[MM*DO];
__device__ float g_r2[MM*DO];
__device__ int   g_deg[NN];
__device__ int   g_off[NN+1];
__device__ int   g_pos[NN];
__device__ int   g_csr[NE];
__device__ int   g_bsum[64];
__device__ __align__(16) uint8_t g_wimg[2*65536 + 2*65536 + 2*32768];

// ---------------- helpers ----------------
__device__ __forceinline__ uint32_t smem_u32(const void* p) {
    uint32_t a;
    asm("{ .reg .u64 t; cvta.to.shared.u64 t, %1; cvt.u32.u64 %0, t; }" : "=r"(a) : "l"(p));
    return a;
}
__device__ __forceinline__ void ldsm4(uint32_t* r, uint32_t addr) {
    asm volatile("ldmatrix.sync.aligned.m8n8.x4.shared.b16 {%0,%1,%2,%3}, [%4];"
        : "=r"(r[0]), "=r"(r[1]), "=r"(r[2]), "=r"(r[3]) : "r"(addr));
}
__device__ __forceinline__ void mma16816(float* c, const uint32_t* a, uint32_t b0, uint32_t b1) {
    asm volatile("mma.sync.aligned.m16n8k16.row.col.f32.bf16.bf16.f32 "
        "{%0,%1,%2,%3}, {%4,%5,%6,%7}, {%8,%9}, {%0,%1,%2,%3};"
        : "+f"(c[0]), "+f"(c[1]), "+f"(c[2]), "+f"(c[3])
        : "r"(a[0]), "r"(a[1]), "r"(a[2]), "r"(a[3]), "r"(b0), "r"(b1));
}
__device__ __forceinline__ void cvt_hilo(const float* v, uint32_t* hp, uint32_t* lp) {
    #pragma unroll
    for (int p = 0; p < 4; p++) {
        __nv_bfloat162 h2 = __floats2bfloat162_rn(v[2*p], v[2*p+1]);
        float l0 = v[2*p]   - __low2float(h2);
        float l1 = v[2*p+1] - __high2float(h2);
        __nv_bfloat162 l2 = __floats2bfloat162_rn(l0, l1);
        hp[p] = *(uint32_t*)&h2;
        lp[p] = *(uint32_t*)&l2;
    }
}

// ---------------- weight image writer ----------------
__device__ __forceinline__ void wconv_item(int id,
        const float* Wl0, const float* Wr0, const float* Wl1, const float* Wr1,
        const float* Wl2, const float* Wr2) {
    const float* src = nullptr;
    uint8_t *imgHi, *imgLo;
    int row, c8;
    if (id < 4096) {
        row = id >> 4; c8 = id & 15;
        imgHi = g_wimg;          imgLo = g_wimg + 65536;
        src = (row < 128) ? (Wl0 + (size_t)row*128) : (Wr0 + (size_t)(row-128)*128);
    } else if (id < 8192) {
        id -= 4096; row = id >> 4; c8 = id & 15;
        imgHi = g_wimg + 131072; imgLo = g_wimg + 196608;
        src = (row < 128) ? (Wl1 + (size_t)row*128) : (Wr1 + (size_t)(row-128)*128);
    } else if (id < 10240) {
        id -= 8192; row = id >> 4; c8 = id & 15;
        imgHi = g_wimg + 262144; imgLo = g_wimg + 294912;
        if (row < 47)                     src = Wl2 + (size_t)row*128;
        else if (row >= 64 && row < 111)  src = Wr2 + (size_t)(row-64)*128;
        else                              src = nullptr;
    } else return;
    float v[8];
    #pragma unroll
    for (int j = 0; j < 8; j++) v[j] = src ? src[c8*8 + j] : 0.f;
    uint32_t hp[4], lp[4];
    cvt_hilo(v, hp, lp);
    uint32_t off = (uint32_t)row*256u + (uint32_t)((c8 ^ (row & 7)) << 4);
    *(uint4*)(imgHi + off) = make_uint4(hp[0], hp[1], hp[2], hp[3]);
    *(uint4*)(imgLo + off) = make_uint4(lp[0], lp[1], lp[2], lp[3]);
}

// ---------------- prep: noise + wconv fused ----------------
#define NOISE_BLOCKS (NN/8)
__global__ void k_prep(const float* __restrict__ x, const float* __restrict__ noise,
                       const float* Wl0, const float* Wr0,
                       const float* Wl1, const float* Wr1,
                       const float* Wl2, const float* Wr2) {
    if (blockIdx.x < NOISE_BLOCKS) {
        int w = (blockIdx.x*blockDim.x + threadIdx.x) >> 5;
        int lane = threadIdx.x & 31;
        const float4 nv = *(const float4*)(noise + (size_t)w*DH + lane*4);
        float ss = nv.x*nv.x + nv.y*nv.y + nv.z*nv.z + nv.w*nv.w;
        #pragma unroll
        for (int o = 16; o; o >>= 1) ss += __shfl_xor_sync(0xffffffffu, ss, o);
        float sc = 0.1f / fmaxf(sqrtf(ss), 1e-12f);
        float4 xv = *(const float4*)(x + (size_t)w*DH + lane*4);
        float4 xn;
        xn.x = xv.x + ((xv.x>0.f)?1.f:((xv.x<0.f)?-1.f:0.f)) * nv.x * sc;
        xn.y = xv.y + ((xv.y>0.f)?1.f:((xv.y<0.f)?-1.f:0.f)) * nv.y * sc;
        xn.z = xv.z + ((xv.z>0.f)?1.f:((xv.z<0.f)?-1.f:0.f)) * nv.z * sc;
        xn.w = xv.w + ((xv.w>0.f)?1.f:((xv.w<0.f)?-1.f:0.f)) * nv.w * sc;
        *(float4*)(g_x2 + (size_t)w*DH      + lane*4) = xv;
        *(float4*)(g_x2 + (size_t)(NN+w)*DH + lane*4) = xn;
    } else {
        int id = (blockIdx.x - NOISE_BLOCKS)*blockDim.x + threadIdx.x;
        wconv_item(id, Wl0, Wr0, Wl1, Wr1, Wl2, Wr2);
    }
}

// ---------------- CSR build ----------------
__global__ void k_zero() {
    int i = blockIdx.x*blockDim.x + threadIdx.x;
    if (i < NN) g_deg[i] = 0;
    if (i < 64) g_bsum[i] = 0;
}
__global__ void k_hist(const int* __restrict__ ei) {
    int e = blockIdx.x*blockDim.x + threadIdx.x;
    if (e < NE) atomicAdd(&g_deg[ei[NE + e]], 1);
}
__global__ void k_scan1() {
    __shared__ int ws[32];
    int tid = threadIdx.x, lane = tid & 31, w = tid >> 5;
    int gid = blockIdx.x*1024 + tid;
    int s = (gid < NN) ? g_deg[gid] : 0;
    #pragma unroll
    for (int o = 1; o < 32; o <<= 1) {
        int t = __shfl_up_sync(0xffffffffu, s, o);
        if (lane >= o) s += t;
    }
    if (lane == 31) ws[w] = s;
    __syncthreads();
    if (w == 0) {
        int x = ws[lane];
        #pragma unroll
        for (int o = 1; o < 32; o <<= 1) {
            int t = __shfl_up_sync(0xffffffffu, x, o);
            if (lane >= o) x += t;
        }
        ws[lane] = x;
    }
    __syncthreads();
    if (w > 0) s += ws[w-1];
    if (gid < NN) g_off[gid+1] = s;
    if (tid == 1023) g_bsum[blockIdx.x] = s;
}
__global__ void k_scan2() {
    __shared__ int s[64];
    int tid = threadIdx.x;
    int v = g_bsum[tid];
    s[tid] = v; __syncthreads();
    for (int o = 1; o < 64; o <<= 1) {
        int t = (tid >= o) ? s[tid-o] : 0;
        __syncthreads(); s[tid] += t; __syncthreads();
    }
    g_bsum[tid] = s[tid] - v;
}
__global__ void k_scan3() {
    int gid = blockIdx.x*1024 + threadIdx.x;
    if (gid >= NN) return;
    int incl = g_off[gid+1] + g_bsum[blockIdx.x];
    g_off[gid+1] = incl;
    g_pos[gid]   = incl - g_deg[gid];
    if (gid == 0) g_off[0] = 0;
}
__global__ void k_fill(const int* __restrict__ ei) {
    int e = blockIdx.x*blockDim.x + threadIdx.x;
    if (e < NE) {
        int dst = ei[NE + e];
        int p = atomicAdd(&g_pos[dst], 1);
        g_csr[p] = ei[e];
    }
}

// ---------------- pipelined mma.sync bf16-split GEMM ----------------
// CTA tile 128x128, 256 thr. smem: Ah[0,32K) Al[32K,64K) Bh[64K,96K) Bl[96K,128K)
// 24 flattened k-steps (3 terms x 8), register double-buffered fragments.
template<bool SPLIT47>
__global__ void __launch_bounds__(256, 1) k_gemm_mma(
    const float* __restrict__ X0, const float* __restrict__ X1, int NSPLIT,
    const uint8_t* __restrict__ imgHi, const uint8_t* __restrict__ imgLo,
    float* __restrict__ out0, float* __restrict__ out1, int M)
{
    extern __shared__ char smem[];
    const int tid = threadIdx.x;
    const int bm = blockIdx.x * 128;
    const int g  = blockIdx.y;
    uint32_t sb = smem_u32(smem);

    // A fill
    #pragma unroll
    for (int i = 0; i < 8; i++) {
        int id = tid + i*256;
        int row = id >> 4, c8 = id & 15;
        int gm = bm + row;
        float v[8];
        if (gm < M) {
            const float* src = (gm < NSPLIT) ? (X0 + (size_t)gm*128)
                                             : (X1 + (size_t)(gm - NSPLIT)*128);
            float4 f0 = *(const float4*)(src + c8*8);
            float4 f1 = *(const float4*)(src + c8*8 + 4);
            v[0]=f0.x; v[1]=f0.y; v[2]=f0.z; v[3]=f0.w;
            v[4]=f1.x; v[5]=f1.y; v[6]=f1.z; v[7]=f1.w;
        } else {
            #pragma unroll
            for (int j = 0; j < 8; j++) v[j] = 0.f;
        }
        uint32_t hp[4], lp[4];
        cvt_hilo(v, hp, lp);
        uint32_t off = (uint32_t)row*256u + (uint32_t)((c8 ^ (row & 7)) << 4);
        *(uint4*)(smem + off)         = make_uint4(hp[0], hp[1], hp[2], hp[3]);
        *(uint4*)(smem + 32768 + off) = make_uint4(lp[0], lp[1], lp[2], lp[3]);
    }
    // B copy (pre-swizzled slice)
    {
        const uint4* bh = (const uint4*)(imgHi + (size_t)g*32768);
        const uint4* bl = (const uint4*)(imgLo + (size_t)g*32768);
        #pragma unroll
        for (int i = 0; i < 8; i++) {
            int id = tid + i*256;
            ((uint4*)(smem + 65536))[id] = bh[id];
            ((uint4*)(smem + 98304))[id] = bl[id];
        }
    }
    __syncthreads();

    const int lane = tid & 31, w = tid >> 5;
    const int tm = (w >> 1) * 32, tn = (w & 1) * 64;
    const int lrow = lane & 15;
    const uint32_t lsel = (uint32_t)(lane >> 4);

    // precomputed ldsm row constants
    uint32_t arc[2], asw[2];
    #pragma unroll
    for (int mt = 0; mt < 2; mt++) {
        int row = tm + mt*16 + lrow;
        arc[mt] = (uint32_t)row*256u; asw[mt] = (uint32_t)(row & 7);
    }
    uint32_t brc[4], bsw[4];
    #pragma unroll
    for (int bt = 0; bt < 4; bt++) {
        int n = tn + bt*16 + lrow;
        brc[bt] = (uint32_t)n*256u; bsw[bt] = (uint32_t)(n & 7);
    }

    float acc[2][8][4];
    #pragma unroll
    for (int a = 0; a < 2; a++)
        #pragma unroll
        for (int b = 0; b < 8; b++)
            #pragma unroll
            for (int c = 0; c < 4; c++) acc[a][b][c] = 0.f;

    uint32_t fa[2][8], fb[2][16];

    // stage loader: s in [0,24), term = s>>3 selects hi/lo images
    #define LOAD_STAGE(buf, s) do { \
        const int _t = (s) >> 3; \
        const uint32_t _c8 = (uint32_t)(((s) & 7)*2) + lsel; \
        uint32_t _ab = sb + (_t == 2 ? 32768u : 0u); \
        uint32_t _bb = sb + (_t == 1 ? 98304u : 65536u); \
        ldsm4(&fa[buf][0], _ab + arc[0] + ((_c8 ^ asw[0]) << 4)); \
        ldsm4(&fa[buf][4], _ab + arc[1] + ((_c8 ^ asw[1]) << 4)); \
        ldsm4(&fb[buf][0],  _bb + brc[0] + ((_c8 ^ bsw[0]) << 4)); \
        ldsm4(&fb[buf][4],  _bb + brc[1] + ((_c8 ^ bsw[1]) << 4)); \
        ldsm4(&fb[buf][8],  _bb + brc[2] + ((_c8 ^ bsw[2]) << 4)); \
        ldsm4(&fb[buf][12], _bb + brc[3] + ((_c8 ^ bsw[3]) << 4)); \
    } while (0)

    LOAD_STAGE(0, 0);
    #pragma unroll
    for (int s = 0; s < 24; s++) {
        const int cur = s & 1;
        if (s < 23) LOAD_STAGE(cur^1, s+1);
        #pragma unroll
        for (int mt = 0; mt < 2; mt++)
            #pragma unroll
            for (int bt = 0; bt < 4; bt++) {
                mma16816(acc[mt][bt*2+0], &fa[cur][mt*4], fb[cur][bt*4+0], fb[cur][bt*4+2]);
                mma16816(acc[mt][bt*2+1], &fa[cur][mt*4], fb[cur][bt*4+1], fb[cur][bt*4+3]);
            }
    }
    #undef LOAD_STAGE

    if constexpr (!SPLIT47) {
        float* dst = g ? out1 : out0;
        #pragma unroll
        for (int mt = 0; mt < 2; mt++) {
            int r0 = bm + tm + mt*16 + (lane >> 2);
            int r1 = r0 + 8;
            #pragma unroll
            for (int nt = 0; nt < 8; nt++) {
                int col = tn + nt*8 + (lane & 3)*2;
                if (r0 < M) *(float2*)(dst + (size_t)r0*128 + col)
                    = make_float2(acc[mt][nt][0], acc[mt][nt][1]);
                if (r1 < M) *(float2*)(dst + (size_t)r1*128 + col)
                    = make_float2(acc[mt][nt][2], acc[mt][nt][3]);
            }
        }
    } else {
        float* dst = (w & 1) ? out1 : out0;   // cols 0-63 -> t2, 64-127 -> r2
        #pragma unroll
        for (int mt = 0; mt < 2; mt++) {
            int r0 = bm + tm + mt*16 + (lane >> 2);
            int r1 = r0 + 8;
            #pragma unroll
            for (int nt = 0; nt < 8; nt++) {
                int cl = nt*8 + (lane & 3)*2;
                if (cl < DO) {
                    if (r0 < M) dst[(size_t)r0*DO + cl] = acc[mt][nt][0];
                    if (r1 < M) dst[(size_t)r1*DO + cl] = acc[mt][nt][2];
                }
                if (cl + 1 < DO) {
                    if (r0 < M) dst[(size_t)r0*DO + cl + 1] = acc[mt][nt][1];
                    if (r1 < M) dst[(size_t)r1*DO + cl + 1] = acc[mt][nt][3];
                }
            }
        }
    }
}

// ---------------- 128-dim mean-agg + bias + self + relu ----------------
__global__ void k_agg128(const float* __restrict__ t, const float* __restrict__ r,
                         const float* __restrict__ bias,
                         float* __restrict__ hout, float* __restrict__ dout)
{
    int w = (blockIdx.x*blockDim.x + threadIdx.x) >> 5;
    int lane = threadIdx.x & 31;
    if (w >= MM) return;
    int b = (w >= NN);
    int i = w - b*NN;
    int base = b*NN;
    int e0 = g_off[i], e1 = g_off[i+1];
    float4 acc = make_float4(0.f,0.f,0.f,0.f);
    for (int e = e0; e < e1; e++) {
        int j = g_csr[e];
        float4 v = *(const float4*)(t + ((size_t)(base + j) << 7) + (lane << 2));
        acc.x += v.x; acc.y += v.y; acc.z += v.z; acc.w += v.w;
    }
    float inv = (e1 > e0) ? 1.f/(float)(e1 - e0) : 0.f;
    float4 bb = *(const float4*)(bias + (lane << 2));
    float4 rr = *(const float4*)(r + ((size_t)w << 7) + (lane << 2));
    float4 o;
    o.x = fmaxf(fmaf(acc.x, inv, bb.x + rr.x), 0.f);
    o.y = fmaxf(fmaf(acc.y, inv, bb.y + rr.y), 0.f);
    o.z = fmaxf(fmaf(acc.z, inv, bb.z + rr.z), 0.f);
    o.w = fmaxf(fmaf(acc.w, inv, bb.w + rr.w), 0.f);
    if (hout) *(float4*)(hout + ((size_t)w << 7) + (lane << 2)) = o;
    if (dout) *(float4*)(dout + (size_t)b*OPB + (size_t)i*DH + (lane << 2)) = o;
}

// ---------------- 47-dim agg + bias + self, z and log_softmax(y) ----------------
__global__ void k_agg47(const float* __restrict__ t2, const float* __restrict__ r2,
                        const float* __restrict__ bias, float* __restrict__ dout)
{
    int w = (blockIdx.x*blockDim.x + threadIdx.x) >> 5;
    int lane = threadIdx.x & 31;
    if (w >= MM) return;
    int b = (w >= NN);
    int i = w - b*NN;
    int base = b*NN;
    int f0 = lane*2, f1 = lane*2 + 1;
    bool v0 = (f0 < DO), v1 = (f1 < DO);
    int e0 = g_off[i], e1 = g_off[i+1];
    float a0 = 0.f, a1 = 0.f;
    for (int e = e0; e < e1; e++) {
        const float* row = t2 + (size_t)(base + g_csr[e]) * DO;
        if (v0) a0 += row[f0];
        if (v1) a1 += row[f1];
    }
    float inv = (e1 > e0) ? 1.f/(float)(e1 - e0) : 0.f;
    float z0 = v0 ? fmaf(a0, inv, bias[f0] + r2[(size_t)w*DO + f0]) : -INFINITY;
    float z1 = v1 ? fmaf(a1, inv, bias[f1] + r2[(size_t)w*DO + f1]) : -INFINITY;
    float m = fmaxf(z0, z1);
    #pragma unroll
    for (int o = 16; o; o >>= 1) m = fmaxf(m, __shfl_xor_sync(0xffffffffu, m, o));
    float s = (v0 ? expf(z0 - m) : 0.f) + (v1 ? expf(z1 - m) : 0.f);
    #pragma unroll
    for (int o = 16; o; o >>= 1) s += __shfl_xor_sync(0xffffffffu, s, o);
    float lse = m + logf(s);
    float* ybase = dout + (size_t)b*OPB + (size_t)NN*DH        + (size_t)i*DO;
    float* zbase = dout + (size_t)b*OPB + (size_t)NN*(DH + DO) + (size_t)i*DO;
    if (v0) { zbase[f0] = z0; ybase[f0] = z0 - lse; }
    if (v1) { zbase[f1] = z1; ybase[f1] = z1 - lse; }
}

// ---------------- orchestration ----------------
extern "C" void kernel_launch(void* const* d_in, const int* in_sizes, int n_in,
                              void* d_out, int out_size)
{
    const float* x     = (const float*)d_in[0];
    const int*   ei    = (const int*)  d_in[1];
    const float* noise = (const float*)d_in[2];
    const float* Wl0   = (const float*)d_in[3];
    const float* bl0   = (const float*)d_in[4];
    const float* Wr0   = (const float*)d_in[5];
    const float* Wl1   = (const float*)d_in[6];
    const float* bl1   = (const float*)d_in[7];
    const float* Wr1   = (const float*)d_in[8];
    const float* Wl2   = (const float*)d_in[9];
    const float* bl2   = (const float*)d_in[10];
    const float* Wr2   = (const float*)d_in[11];
    float* out = (float*)d_out;

    float *px2, *pt, *pr, *ph, *pt2, *pr2;
    uint8_t* pw;
    cudaGetSymbolAddress((void**)&px2, g_x2);
    cudaGetSymbolAddress((void**)&pt,  g_t);
    cudaGetSymbolAddress((void**)&pr,  g_r);
    cudaGetSymbolAddress((void**)&ph,  g_h);
    cudaGetSymbolAddress((void**)&pt2, g_t2);
    cudaGetSymbolAddress((void**)&pr2, g_r2);
    cudaGetSymbolAddress((void**)&pw,  g_wimg);

    const int SM = 131072;
    cudaFuncSetAttribute(k_gemm_mma<false>, cudaFuncAttributeMaxDynamicSharedMemorySize, SM);
    cudaFuncSetAttribute(k_gemm_mma<true>,  cudaFuncAttributeMaxDynamicSharedMemorySize, SM);

    int gBlocks = (MM + 127)/128;        // 782
    dim3 gBig(gBlocks, 2);
    dim3 gSml(gBlocks, 1);
    int aggBlocks = (MM*32 + 255)/256;

    // idx 0: noise + weight conversion (fused)
    k_prep<<<NOISE_BLOCKS + 40, 256>>>(x, noise, Wl0, Wr0, Wl1, Wr1, Wl2, Wr2);
    // idx 1-2
    k_zero <<<(NN + 255)/256, 256>>>();
    k_hist <<<(NE + 255)/256, 256>>>(ei);
    // idx 3: layer-0 GEMM (ncu capture target)
    k_gemm_mma<false><<<gBig, 256, SM>>>(px2, px2, MM, pw, pw + 65536, pt, pr, MM);
    // idx 4-7: finish CSR
    k_scan1<<<NB_SCAN, 1024>>>();
    k_scan2<<<1, 64>>>();
    k_scan3<<<NB_SCAN, 1024>>>();
    k_fill <<<(NE + 255)/256, 256>>>(ei);
    // layer 0 agg -> h1
    k_agg128<<<aggBlocks, 256>>>(pt, pr, bl0, ph, nullptr);
    // layer 1
    k_gemm_mma<false><<<gBig, 256, SM>>>(ph, ph, MM, pw + 131072, pw + 196608, pt, pr, MM);
    k_agg128<<<aggBlocks, 256>>>(pt, pr, bl1, nullptr, out);
    // layer 2 (reads h2 from d_out)
    k_gemm_mma<true><<<gSml, 256, SM>>>(out, out + OPB, NN,
                                        pw + 262144, pw + 294912, pt2, pr2, MM);
    k_agg47<<<aggBlocks, 256>>>(pt2, pr2, bl2, out);
}

// round 8
// speedup vs baseline: 1.2294x; 1.2065x over previous
#include <cuda_runtime.h>
#include <cuda_bf16.h>
#include <cuda_fp16.h>
#include <math.h>
#include <stdint.h>

#define NN 50000
#define NE 800000
#define DH 128
#define DO 47
#define MM (2*NN)
#define OPB (NN*(DH+DO+DO))
#define NB_SCAN ((NN + 1023)/1024)

// ---------------- scratch ----------------
__device__ float g_x2[MM*DH];
__device__ float g_t [MM*DH];     // t as fp16x2 (MM x 64 u32) for 128-dim layers
__device__ float g_r [MM*DH];
__device__ float g_h [MM*DH];
__device__ float g_t2[MM*DO];
__device__ float g_r2[MM*DO];
__device__ int   g_deg[NN];
__device__ int   g_off[NN+1];
__device__ int   g_pos[NN];
__device__ int   g_csr[NE];
__device__ int   g_bsum[64];
// weight images: per slice g: [kh][n][128B] swizzled. L0 hi/lo 64KB, L1 hi/lo, L2 hi/lo 32KB
__device__ __align__(16) uint8_t g_wimg[2*65536 + 2*65536 + 2*32768];

// ---------------- helpers ----------------
__device__ __forceinline__ uint32_t smem_u32(const void* p) {
    uint32_t a;
    asm("{ .reg .u64 t; cvta.to.shared.u64 t, %1; cvt.u32.u64 %0, t; }" : "=r"(a) : "l"(p));
    return a;
}
__device__ __forceinline__ void ldsm4(uint32_t* r, uint32_t addr) {
    asm volatile("ldmatrix.sync.aligned.m8n8.x4.shared.b16 {%0,%1,%2,%3}, [%4];"
        : "=r"(r[0]), "=r"(r[1]), "=r"(r[2]), "=r"(r[3]) : "r"(addr));
}
__device__ __forceinline__ void mma16816(float* c, const uint32_t* a, uint32_t b0, uint32_t b1) {
    asm volatile("mma.sync.aligned.m16n8k16.row.col.f32.bf16.bf16.f32 "
        "{%0,%1,%2,%3}, {%4,%5,%6,%7}, {%8,%9}, {%0,%1,%2,%3};"
        : "+f"(c[0]), "+f"(c[1]), "+f"(c[2]), "+f"(c[3])
        : "r"(a[0]), "r"(a[1]), "r"(a[2]), "r"(a[3]), "r"(b0), "r"(b1));
}
__device__ __forceinline__ void cvt_hilo(const float* v, uint32_t* hp, uint32_t* lp) {
    #pragma unroll
    for (int p = 0; p < 4; p++) {
        __nv_bfloat162 h2 = __floats2bfloat162_rn(v[2*p], v[2*p+1]);
        float l0 = v[2*p]   - __low2float(h2);
        float l1 = v[2*p+1] - __high2float(h2);
        __nv_bfloat162 l2 = __floats2bfloat162_rn(l0, l1);
        hp[p] = *(uint32_t*)&h2;
        lp[p] = *(uint32_t*)&l2;
    }
}
__device__ __forceinline__ uint32_t pack_h2(float a, float b) {
    __half2 h = __floats2half2_rn(a, b);
    return *(uint32_t*)&h;
}

// ---------------- weight image writer: [g 32KB][kh 16KB][n 128B] ----------------
__device__ __forceinline__ void wconv_item(int id,
        const float* Wl0, const float* Wr0, const float* Wl1, const float* Wr1,
        const float* Wl2, const float* Wr2) {
    const float* src = nullptr;
    uint8_t *imgHi, *imgLo;
    int row, c8;
    if (id < 4096) {
        row = id >> 4; c8 = id & 15;
        imgHi = g_wimg;          imgLo = g_wimg + 65536;
        src = (row < 128) ? (Wl0 + (size_t)row*128) : (Wr0 + (size_t)(row-128)*128);
    } else if (id < 8192) {
        id -= 4096; row = id >> 4; c8 = id & 15;
        imgHi = g_wimg + 131072; imgLo = g_wimg + 196608;
        src = (row < 128) ? (Wl1 + (size_t)row*128) : (Wr1 + (size_t)(row-128)*128);
    } else if (id < 10240) {
        id -= 8192; row = id >> 4; c8 = id & 15;
        imgHi = g_wimg + 262144; imgLo = g_wimg + 294912;
        if (row < 47)                     src = Wl2 + (size_t)row*128;
        else if (row >= 64 && row < 111)  src = Wr2 + (size_t)(row-64)*128;
        else                              src = nullptr;
    } else return;
    float v[8];
    #pragma unroll
    for (int j = 0; j < 8; j++) v[j] = src ? src[c8*8 + j] : 0.f;
    uint32_t hp[4], lp[4];
    cvt_hilo(v, hp, lp);
    int gsl = row >> 7, n = row & 127;
    int kh = c8 >> 3, c8l = c8 & 7;
    uint32_t off = (uint32_t)gsl*32768u + (uint32_t)kh*16384u
                 + (uint32_t)n*128u + (uint32_t)((c8l ^ (n & 7)) << 4);
    *(uint4*)(imgHi + off) = make_uint4(hp[0], hp[1], hp[2], hp[3]);
    *(uint4*)(imgLo + off) = make_uint4(lp[0], lp[1], lp[2], lp[3]);
}

// ---------------- prep: noise + wconv fused ----------------
#define NOISE_BLOCKS (NN/8)
__global__ void k_prep(const float* __restrict__ x, const float* __restrict__ noise,
                       const float* Wl0, const float* Wr0,
                       const float* Wl1, const float* Wr1,
                       const float* Wl2, const float* Wr2) {
    if (blockIdx.x < NOISE_BLOCKS) {
        int w = (blockIdx.x*blockDim.x + threadIdx.x) >> 5;
        int lane = threadIdx.x & 31;
        const float4 nv = *(const float4*)(noise + (size_t)w*DH + lane*4);
        float ss = nv.x*nv.x + nv.y*nv.y + nv.z*nv.z + nv.w*nv.w;
        #pragma unroll
        for (int o = 16; o; o >>= 1) ss += __shfl_xor_sync(0xffffffffu, ss, o);
        float sc = 0.1f / fmaxf(sqrtf(ss), 1e-12f);
        float4 xv = *(const float4*)(x + (size_t)w*DH + lane*4);
        float4 xn;
        xn.x = xv.x + ((xv.x>0.f)?1.f:((xv.x<0.f)?-1.f:0.f)) * nv.x * sc;
        xn.y = xv.y + ((xv.y>0.f)?1.f:((xv.y<0.f)?-1.f:0.f)) * nv.y * sc;
        xn.z = xv.z + ((xv.z>0.f)?1.f:((xv.z<0.f)?-1.f:0.f)) * nv.z * sc;
        xn.w = xv.w + ((xv.w>0.f)?1.f:((xv.w<0.f)?-1.f:0.f)) * nv.w * sc;
        *(float4*)(g_x2 + (size_t)w*DH      + lane*4) = xv;
        *(float4*)(g_x2 + (size_t)(NN+w)*DH + lane*4) = xn;
    } else {
        int id = (blockIdx.x - NOISE_BLOCKS)*blockDim.x + threadIdx.x;
        wconv_item(id, Wl0, Wr0, Wl1, Wr1, Wl2, Wr2);
    }
}

// ---------------- CSR build ----------------
__global__ void k_zero() {
    int i = blockIdx.x*blockDim.x + threadIdx.x;
    if (i < NN) g_deg[i] = 0;
    if (i < 64) g_bsum[i] = 0;
}
__global__ void k_hist(const int* __restrict__ ei) {
    int e = blockIdx.x*blockDim.x + threadIdx.x;
    if (e < NE) atomicAdd(&g_deg[ei[NE + e]], 1);
}
__global__ void k_scan1() {
    __shared__ int ws[32];
    int tid = threadIdx.x, lane = tid & 31, w = tid >> 5;
    int gid = blockIdx.x*1024 + tid;
    int s = (gid < NN) ? g_deg[gid] : 0;
    #pragma unroll
    for (int o = 1; o < 32; o <<= 1) {
        int t = __shfl_up_sync(0xffffffffu, s, o);
        if (lane >= o) s += t;
    }
    if (lane == 31) ws[w] = s;
    __syncthreads();
    if (w == 0) {
        int x = ws[lane];
        #pragma unroll
        for (int o = 1; o < 32; o <<= 1) {
            int t = __shfl_up_sync(0xffffffffu, x, o);
            if (lane >= o) x += t;
        }
        ws[lane] = x;
    }
    __syncthreads();
    if (w > 0) s += ws[w-1];
    if (gid < NN) g_off[gid+1] = s;
    if (tid == 1023) g_bsum[blockIdx.x] = s;
}
__global__ void k_scan2() {
    __shared__ int s[64];
    int tid = threadIdx.x;
    int v = g_bsum[tid];
    s[tid] = v; __syncthreads();
    for (int o = 1; o < 64; o <<= 1) {
        int t = (tid >= o) ? s[tid-o] : 0;
        __syncthreads(); s[tid] += t; __syncthreads();
    }
    g_bsum[tid] = s[tid] - v;
}
__global__ void k_scan3() {
    int gid = blockIdx.x*1024 + threadIdx.x;
    if (gid >= NN) return;
    int incl = g_off[gid+1] + g_bsum[blockIdx.x];
    g_off[gid+1] = incl;
    g_pos[gid]   = incl - g_deg[gid];
    if (gid == 0) g_off[0] = 0;
}
__global__ void k_fill(const int* __restrict__ ei) {
    int e = blockIdx.x*blockDim.x + threadIdx.x;
    if (e < NE) {
        int dst = ei[NE + e];
        int p = atomicAdd(&g_pos[dst], 1);
        g_csr[p] = ei[e];
    }
}

// ---------------- bf16-split GEMM, 96KB smem, 2 CTA/SM ----------------
// smem: Ah[0,32K) Al[32K,64K) Bh[64K,80K) Bl[80K,96K). B staged in K-halves.
// !SPLIT47: g==0 -> out0 packed fp16x2 (stride 64 u32); g==1 -> out1 fp32 (stride 128)
// SPLIT47:  cols 0-63 -> out0 fp32 (stride DO), 64-127 -> out1 (stride DO)
template<bool SPLIT47>
__global__ void __launch_bounds__(256, 2) k_gemm_mma(
    const float* __restrict__ X0, const float* __restrict__ X1, int NSPLIT,
    const uint8_t* __restrict__ imgHi, const uint8_t* __restrict__ imgLo,
    void* __restrict__ out0, float* __restrict__ out1, int M)
{
    extern __shared__ char smem[];
    const int tid = threadIdx.x;
    const int bm = blockIdx.x * 128;
    const int g  = blockIdx.y;
    uint32_t sb = smem_u32(smem);

    // A fill (full K, 256B rows)
    #pragma unroll
    for (int i = 0; i < 8; i++) {
        int id = tid + i*256;
        int row = id >> 4, c8 = id & 15;
        int gm = bm + row;
        float v[8];
        if (gm < M) {
            const float* src = (gm < NSPLIT) ? (X0 + (size_t)gm*128)
                                             : (X1 + (size_t)(gm - NSPLIT)*128);
            float4 f0 = *(const float4*)(src + c8*8);
            float4 f1 = *(const float4*)(src + c8*8 + 4);
            v[0]=f0.x; v[1]=f0.y; v[2]=f0.z; v[3]=f0.w;
            v[4]=f1.x; v[5]=f1.y; v[6]=f1.z; v[7]=f1.w;
        } else {
            #pragma unroll
            for (int j = 0; j < 8; j++) v[j] = 0.f;
        }
        uint32_t hp[4], lp[4];
        cvt_hilo(v, hp, lp);
        uint32_t off = (uint32_t)row*256u + (uint32_t)((c8 ^ (row & 7)) << 4);
        *(uint4*)(smem + off)         = make_uint4(hp[0], hp[1], hp[2], hp[3]);
        *(uint4*)(smem + 32768 + off) = make_uint4(lp[0], lp[1], lp[2], lp[3]);
    }

    const int lane = tid & 31, w = tid >> 5;
    const int tm = (w >> 1) * 32, tn = (w & 1) * 64;
    const int lrow = lane & 15;
    const uint32_t lsel = (uint32_t)(lane >> 4);

    float acc[2][8][4];
    #pragma unroll
    for (int a = 0; a < 2; a++)
        #pragma unroll
        for (int b = 0; b < 8; b++)
            #pragma unroll
            for (int c = 0; c < 4; c++) acc[a][b][c] = 0.f;

    const uint4* bh = (const uint4*)(imgHi + (size_t)g*32768);
    const uint4* bl = (const uint4*)(imgLo + (size_t)g*32768);

    #pragma unroll
    for (int kh = 0; kh < 2; kh++) {
        __syncthreads();   // A-fill done (kh=0) / previous compute done (kh=1)
        // stage B K-half: 16KB hi + 16KB lo
        #pragma unroll
        for (int i = 0; i < 4; i++) {
            int id = tid + i*256;
            ((uint4*)(smem + 65536))[id] = bh[kh*1024 + id];
            ((uint4*)(smem + 81920))[id] = bl[kh*1024 + id];
        }
        __syncthreads();
        #pragma unroll
        for (int term = 0; term < 3; term++) {
            uint32_t abase = sb + (term == 2 ? 32768u : 0u);
            uint32_t bbase = sb + (term == 1 ? 81920u : 65536u);
            #pragma unroll
            for (int k16 = 0; k16 < 4; k16++) {
                const uint32_t c8a = (uint32_t)(kh*8 + k16*2) + lsel;
                const uint32_t c8b = (uint32_t)(k16*2) + lsel;
                uint32_t a[2][4];
                #pragma unroll
                for (int mt = 0; mt < 2; mt++) {
                    int row = tm + mt*16 + lrow;
                    ldsm4(a[mt], abase + (uint32_t)row*256u + ((c8a ^ (uint32_t)(row & 7)) << 4));
                }
                uint32_t b[4][4];
                #pragma unroll
                for (int bt = 0; bt < 4; bt++) {
                    int n = tn + bt*16 + lrow;
                    ldsm4(b[bt], bbase + (uint32_t)n*128u + ((c8b ^ (uint32_t)(n & 7)) << 4));
                }
                #pragma unroll
                for (int mt = 0; mt < 2; mt++)
                    #pragma unroll
                    for (int bt = 0; bt < 4; bt++) {
                        mma16816(acc[mt][bt*2+0], a[mt], b[bt][0], b[bt][2]);
                        mma16816(acc[mt][bt*2+1], a[mt], b[bt][1], b[bt][3]);
                    }
            }
        }
    }

    if constexpr (!SPLIT47) {
        if (g == 0) {   // t: packed fp16x2, row stride 64 u32
            uint32_t* dst = (uint32_t*)out0;
            #pragma unroll
            for (int mt = 0; mt < 2; mt++) {
                int r0 = bm + tm + mt*16 + (lane >> 2);
                int r1 = r0 + 8;
                #pragma unroll
                for (int nt = 0; nt < 8; nt++) {
                    int cp = (tn + nt*8 + (lane & 3)*2) >> 1;
                    if (r0 < M) dst[(size_t)r0*64 + cp] = pack_h2(acc[mt][nt][0], acc[mt][nt][1]);
                    if (r1 < M) dst[(size_t)r1*64 + cp] = pack_h2(acc[mt][nt][2], acc[mt][nt][3]);
                }
            }
        } else {        // r: fp32, stride 128
            #pragma unroll
            for (int mt = 0; mt < 2; mt++) {
                int r0 = bm + tm + mt*16 + (lane >> 2);
                int r1 = r0 + 8;
                #pragma unroll
                for (int nt = 0; nt < 8; nt++) {
                    int col = tn + nt*8 + (lane & 3)*2;
                    if (r0 < M) *(float2*)(out1 + (size_t)r0*128 + col)
                        = make_float2(acc[mt][nt][0], acc[mt][nt][1]);
                    if (r1 < M) *(float2*)(out1 + (size_t)r1*128 + col)
                        = make_float2(acc[mt][nt][2], acc[mt][nt][3]);
                }
            }
        }
    } else {
        float* dst = (w & 1) ? out1 : (float*)out0;
        #pragma unroll
        for (int mt = 0; mt < 2; mt++) {
            int r0 = bm + tm + mt*16 + (lane >> 2);
            int r1 = r0 + 8;
            #pragma unroll
            for (int nt = 0; nt < 8; nt++) {
                int cl = nt*8 + (lane & 3)*2;
                if (cl < DO) {
                    if (r0 < M) dst[(size_t)r0*DO + cl] = acc[mt][nt][0];
                    if (r1 < M) dst[(size_t)r1*DO + cl] = acc[mt][nt][2];
                }
                if (cl + 1 < DO) {
                    if (r0 < M) dst[(size_t)r0*DO + cl + 1] = acc[mt][nt][1];
                    if (r1 < M) dst[(size_t)r1*DO + cl + 1] = acc[mt][nt][3];
                }
            }
        }
    }
}

// ---------------- 128-dim mean-agg (fp16 t, MLP-4) + bias + self + relu ----------------
__global__ void k_agg128(const uint32_t* __restrict__ t, const float* __restrict__ r,
                         const float* __restrict__ bias,
                         float* __restrict__ hout, float* __restrict__ dout)
{
    int w = (blockIdx.x*blockDim.x + threadIdx.x) >> 5;
    int lane = threadIdx.x & 31;
    if (w >= MM) return;
    int b = (w >= NN);
    int i = w - b*NN;
    int base = b*NN;
    int e0 = g_off[i], e1 = g_off[i+1];
    float4 acc0 = make_float4(0.f,0.f,0.f,0.f);
    float4 acc1 = make_float4(0.f,0.f,0.f,0.f);
    int e = e0;
    for (; e + 4 <= e1; e += 4) {
        int j0 = g_csr[e], j1 = g_csr[e+1], j2 = g_csr[e+2], j3 = g_csr[e+3];
        uint2 u0 = *(const uint2*)(t + ((size_t)(base + j0) << 6) + (lane << 1));
        uint2 u1 = *(const uint2*)(t + ((size_t)(base + j1) << 6) + (lane << 1));
        uint2 u2 = *(const uint2*)(t + ((size_t)(base + j2) << 6) + (lane << 1));
        uint2 u3 = *(const uint2*)(t + ((size_t)(base + j3) << 6) + (lane << 1));
        float2 a0 = __half22float2(*(__half2*)&u0.x), b0 = __half22float2(*(__half2*)&u0.y);
        float2 a1 = __half22float2(*(__half2*)&u1.x), b1 = __half22float2(*(__half2*)&u1.y);
        float2 a2 = __half22float2(*(__half2*)&u2.x), b2 = __half22float2(*(__half2*)&u2.y);
        float2 a3 = __half22float2(*(__half2*)&u3.x), b3 = __half22float2(*(__half2*)&u3.y);
        acc0.x += a0.x + a1.x; acc0.y += a0.y + a1.y;
        acc0.z += b0.x + b1.x; acc0.w += b0.y + b1.y;
        acc1.x += a2.x + a3.x; acc1.y += a2.y + a3.y;
        acc1.z += b2.x + b3.x; acc1.w += b2.y + b3.y;
    }
    for (; e < e1; e++) {
        int j = g_csr[e];
        uint2 u = *(const uint2*)(t + ((size_t)(base + j) << 6) + (lane << 1));
        float2 a = __half22float2(*(__half2*)&u.x), bb = __half22float2(*(__half2*)&u.y);
        acc0.x += a.x; acc0.y += a.y; acc0.z += bb.x; acc0.w += bb.y;
    }
    float4 acc = make_float4(acc0.x + acc1.x, acc0.y + acc1.y,
                             acc0.z + acc1.z, acc0.w + acc1.w);
    float inv = (e1 > e0) ? 1.f/(float)(e1 - e0) : 0.f;
    float4 bb = *(const float4*)(bias + (lane << 2));
    float4 rr = *(const float4*)(r + ((size_t)w << 7) + (lane << 2));
    float4 o;
    o.x = fmaxf(fmaf(acc.x, inv, bb.x + rr.x), 0.f);
    o.y = fmaxf(fmaf(acc.y, inv, bb.y + rr.y), 0.f);
    o.z = fmaxf(fmaf(acc.z, inv, bb.z + rr.z), 0.f);
    o.w = fmaxf(fmaf(acc.w, inv, bb.w + rr.w), 0.f);
    if (hout) *(float4*)(hout + ((size_t)w << 7) + (lane << 2)) = o;
    if (dout) *(float4*)(dout + (size_t)b*OPB + (size_t)i*DH + (lane << 2)) = o;
}

// ---------------- 47-dim agg (fp32, MLP-4) + log_softmax ----------------
__global__ void k_agg47(const float* __restrict__ t2, const float* __restrict__ r2,
                        const float* __restrict__ bias, float* __restrict__ dout)
{
    int w = (blockIdx.x*blockDim.x + threadIdx.x) >> 5;
    int lane = threadIdx.x & 31;
    if (w >= MM) return;
    int b = (w >= NN);
    int i = w - b*NN;
    int base = b*NN;
    int f0 = lane*2, f1 = lane*2 + 1;
    bool v0 = (f0 < DO), v1 = (f1 < DO);
    int e0 = g_off[i], e1 = g_off[i+1];
    float a0 = 0.f, a1 = 0.f, c0 = 0.f, c1 = 0.f;
    int e = e0;
    for (; e + 2 <= e1; e += 2) {
        const float* rowA = t2 + (size_t)(base + g_csr[e])   * DO;
        const float* rowB = t2 + (size_t)(base + g_csr[e+1]) * DO;
        if (v0) { a0 += rowA[f0]; c0 += rowB[f0]; }
        if (v1) { a1 += rowA[f1]; c1 += rowB[f1]; }
    }
    for (; e < e1; e++) {
        const float* row = t2 + (size_t)(base + g_csr[e]) * DO;
        if (v0) a0 += row[f0];
        if (v1) a1 += row[f1];
    }
    a0 += c0; a1 += c1;
    float inv = (e1 > e0) ? 1.f/(float)(e1 - e0) : 0.f;
    float z0 = v0 ? fmaf(a0, inv, bias[f0] + r2[(size_t)w*DO + f0]) : -INFINITY;
    float z1 = v1 ? fmaf(a1, inv, bias[f1] + r2[(size_t)w*DO + f1]) : -INFINITY;
    float m = fmaxf(z0, z1);
    #pragma unroll
    for (int o = 16; o; o >>= 1) m = fmaxf(m, __shfl_xor_sync(0xffffffffu, m, o));
    float s = (v0 ? expf(z0 - m) : 0.f) + (v1 ? expf(z1 - m) : 0.f);
    #pragma unroll
    for (int o = 16; o; o >>= 1) s += __shfl_xor_sync(0xffffffffu, s, o);
    float lse = m + logf(s);
    float* ybase = dout + (size_t)b*OPB + (size_t)NN*DH        + (size_t)i*DO;
    float* zbase = dout + (size_t)b*OPB + (size_t)NN*(DH + DO) + (size_t)i*DO;
    if (v0) { zbase[f0] = z0; ybase[f0] = z0 - lse; }
    if (v1) { zbase[f1] = z1; ybase[f1] = z1 - lse; }
}

// ---------------- orchestration ----------------
extern "C" void kernel_launch(void* const* d_in, const int* in_sizes, int n_in,
                              void* d_out, int out_size)
{
    const float* x     = (const float*)d_in[0];
    const int*   ei    = (const int*)  d_in[1];
    const float* noise = (const float*)d_in[2];
    const float* Wl0   = (const float*)d_in[3];
    const float* bl0   = (const float*)d_in[4];
    const float* Wr0   = (const float*)d_in[5];
    const float* Wl1   = (const float*)d_in[6];
    const float* bl1   = (const float*)d_in[7];
    const float* Wr1   = (const float*)d_in[8];
    const float* Wl2   = (const float*)d_in[9];
    const float* bl2   = (const float*)d_in[10];
    const float* Wr2   = (const float*)d_in[11];
    float* out = (float*)d_out;

    float *px2, *pt, *pr, *ph, *pt2, *pr2;
    uint8_t* pw;
    cudaGetSymbolAddress((void**)&px2, g_x2);
    cudaGetSymbolAddress((void**)&pt,  g_t);
    cudaGetSymbolAddress((void**)&pr,  g_r);
    cudaGetSymbolAddress((void**)&ph,  g_h);
    cudaGetSymbolAddress((void**)&pt2, g_t2);
    cudaGetSymbolAddress((void**)&pr2, g_r2);
    cudaGetSymbolAddress((void**)&pw,  g_wimg);

    const int SM = 98304;   // 96KB -> 2 CTAs/SM
    cudaFuncSetAttribute(k_gemm_mma<false>, cudaFuncAttributeMaxDynamicSharedMemorySize, SM);
    cudaFuncSetAttribute(k_gemm_mma<true>,  cudaFuncAttributeMaxDynamicSharedMemorySize, SM);

    int gBlocks = (MM + 127)/128;
    dim3 gBig(gBlocks, 2);
    dim3 gSml(gBlocks, 1);
    int aggBlocks = (MM*32 + 255)/256;

    // idx 0: noise + weight conversion
    k_prep<<<NOISE_BLOCKS + 40, 256>>>(x, noise, Wl0, Wr0, Wl1, Wr1, Wl2, Wr2);
    // idx 1-2
    k_zero <<<(NN + 255)/256, 256>>>();
    k_hist <<<(NE + 255)/256, 256>>>(ei);
    // idx 3: layer-0 GEMM (ncu capture target)
    k_gemm_mma<false><<<gBig, 256, SM>>>(px2, px2, MM, pw, pw + 65536, pt, pr, MM);
    // idx 4-7: finish CSR
    k_scan1<<<NB_SCAN, 1024>>>();
    k_scan2<<<1, 64>>>();
    k_scan3<<<NB_SCAN, 1024>>>();
    k_fill <<<(NE + 255)/256, 256>>>(ei);
    // layer 0 agg -> h1
    k_agg128<<<aggBlocks, 256>>>((const uint32_t*)pt, pr, bl0, ph, nullptr);
    // layer 1
    k_gemm_mma<false><<<gBig, 256, SM>>>(ph, ph, MM, pw + 131072, pw + 196608, pt, pr, MM);
    k_agg128<<<aggBlocks, 256>>>((const uint32_t*)pt, pr, bl1, nullptr, out);
    // layer 2 (reads h2 from d_out)
    k_gemm_mma<true><<<gSml, 256, SM>>>(out, out + OPB, NN,
                                        pw + 262144, pw + 294912, pt2, pr2, MM);
    k_agg47<<<aggBlocks, 256>>>(pt2, pr2, bl2, out);
}

// round 9
// speedup vs baseline: 1.4857x; 1.2085x over previous
#include <cuda_runtime.h>
#include <cuda_bf16.h>
#include <cuda_fp16.h>
#include <math.h>
#include <stdint.h>

#define NN 50000
#define NE 800000
#define DH 128
#define DO 47
#define MM (2*NN)
#define OPB (NN*(DH+DO+DO))
#define NB_SCAN ((NN + 1023)/1024)

// ---------------- scratch ----------------
__device__ float g_x2[MM*DH];
__device__ float g_t [MM*DH];     // t as fp16x2 (MM x 64 u32)
__device__ float g_r [MM*DH];
__device__ float g_h [MM*DH];
__device__ float g_t2[MM*DO];
__device__ float g_r2[MM*DO];
__device__ int   g_deg[NN];
__device__ int   g_off[NN+1];
__device__ int   g_pos[NN];
__device__ int   g_csr[NE];
__device__ int   g_bsum[64];
// fp16 weight images, [g-slice 32KB][n row 256B] chunk-swizzled:
// L0 hi 64K, lo 64K; L1 hi, lo; L2 hi 32K, lo 32K
__device__ __align__(16) uint8_t g_wimg[2*65536 + 2*65536 + 2*32768];

// ---------------- helpers ----------------
__device__ __forceinline__ uint32_t smem_u32(const void* p) {
    uint32_t a;
    asm("{ .reg .u64 t; cvta.to.shared.u64 t, %1; cvt.u32.u64 %0, t; }" : "=r"(a) : "l"(p));
    return a;
}
__device__ __forceinline__ void ldsm4(uint32_t* r, uint32_t addr) {
    asm volatile("ldmatrix.sync.aligned.m8n8.x4.shared.b16 {%0,%1,%2,%3}, [%4];"
        : "=r"(r[0]), "=r"(r[1]), "=r"(r[2]), "=r"(r[3]) : "r"(addr));
}
__device__ __forceinline__ void mma16816(float* c, const uint32_t* a, uint32_t b0, uint32_t b1) {
    asm volatile("mma.sync.aligned.m16n8k16.row.col.f32.f16.f16.f32 "
        "{%0,%1,%2,%3}, {%4,%5,%6,%7}, {%8,%9}, {%0,%1,%2,%3};"
        : "+f"(c[0]), "+f"(c[1]), "+f"(c[2]), "+f"(c[3])
        : "r"(a[0]), "r"(a[1]), "r"(a[2]), "r"(a[3]), "r"(b0), "r"(b1));
}
__device__ __forceinline__ uint32_t pack_h2(float a, float b) {
    __half2 h = __floats2half2_rn(a, b);
    return *(uint32_t*)&h;
}
// fp16 hi/lo split: hi = fp16(v), lo = fp16(v - hi)
__device__ __forceinline__ void cvt_hilo16(const float* v, uint32_t* hp, uint32_t* lp) {
    #pragma unroll
    for (int p = 0; p < 4; p++) {
        __half2 h2 = __floats2half2_rn(v[2*p], v[2*p+1]);
        float l0 = v[2*p]   - __low2float(h2);
        float l1 = v[2*p+1] - __high2float(h2);
        __half2 l2 = __floats2half2_rn(l0, l1);
        hp[p] = *(uint32_t*)&h2;
        lp[p] = *(uint32_t*)&l2;
    }
}

// ---------------- weight image writer: [g 32KB][n][256B] ----------------
__device__ __forceinline__ void wconv_item(int id,
        const float* Wl0, const float* Wr0, const float* Wl1, const float* Wr1,
        const float* Wl2, const float* Wr2) {
    const float* src = nullptr;
    uint8_t *imgHi, *imgLo;
    int row, c8;
    if (id < 4096) {
        row = id >> 4; c8 = id & 15;
        imgHi = g_wimg;          imgLo = g_wimg + 65536;
        src = (row < 128) ? (Wl0 + (size_t)row*128) : (Wr0 + (size_t)(row-128)*128);
    } else if (id < 8192) {
        id -= 4096; row = id >> 4; c8 = id & 15;
        imgHi = g_wimg + 131072; imgLo = g_wimg + 196608;
        src = (row < 128) ? (Wl1 + (size_t)row*128) : (Wr1 + (size_t)(row-128)*128);
    } else if (id < 10240) {
        id -= 8192; row = id >> 4; c8 = id & 15;
        imgHi = g_wimg + 262144; imgLo = g_wimg + 294912;
        if (row < 47)                     src = Wl2 + (size_t)row*128;
        else if (row >= 64 && row < 111)  src = Wr2 + (size_t)(row-64)*128;
        else                              src = nullptr;
    } else return;
    float v[8];
    #pragma unroll
    for (int j = 0; j < 8; j++) v[j] = src ? src[c8*8 + j] : 0.f;
    uint32_t hp[4], lp[4];
    cvt_hilo16(v, hp, lp);
    int gsl = row >> 7, n = row & 127;
    uint32_t off = (uint32_t)gsl*32768u + (uint32_t)n*256u
                 + (uint32_t)((c8 ^ (n & 7)) << 4);
    *(uint4*)(imgHi + off) = make_uint4(hp[0], hp[1], hp[2], hp[3]);
    *(uint4*)(imgLo + off) = make_uint4(lp[0], lp[1], lp[2], lp[3]);
}

// ---------------- prep: noise + wconv fused ----------------
#define NOISE_BLOCKS (NN/8)
__global__ void k_prep(const float* __restrict__ x, const float* __restrict__ noise,
                       const float* Wl0, const float* Wr0,
                       const float* Wl1, const float* Wr1,
                       const float* Wl2, const float* Wr2) {
    if (blockIdx.x < NOISE_BLOCKS) {
        int w = (blockIdx.x*blockDim.x + threadIdx.x) >> 5;
        int lane = threadIdx.x & 31;
        const float4 nv = *(const float4*)(noise + (size_t)w*DH + lane*4);
        float ss = nv.x*nv.x + nv.y*nv.y + nv.z*nv.z + nv.w*nv.w;
        #pragma unroll
        for (int o = 16; o; o >>= 1) ss += __shfl_xor_sync(0xffffffffu, ss, o);
        float sc = 0.1f / fmaxf(sqrtf(ss), 1e-12f);
        float4 xv = *(const float4*)(x + (size_t)w*DH + lane*4);
        float4 xn;
        xn.x = xv.x + ((xv.x>0.f)?1.f:((xv.x<0.f)?-1.f:0.f)) * nv.x * sc;
        xn.y = xv.y + ((xv.y>0.f)?1.f:((xv.y<0.f)?-1.f:0.f)) * nv.y * sc;
        xn.z = xv.z + ((xv.z>0.f)?1.f:((xv.z<0.f)?-1.f:0.f)) * nv.z * sc;
        xn.w = xv.w + ((xv.w>0.f)?1.f:((xv.w<0.f)?-1.f:0.f)) * nv.w * sc;
        *(float4*)(g_x2 + (size_t)w*DH      + lane*4) = xv;
        *(float4*)(g_x2 + (size_t)(NN+w)*DH + lane*4) = xn;
    } else {
        int id = (blockIdx.x - NOISE_BLOCKS)*blockDim.x + threadIdx.x;
        wconv_item(id, Wl0, Wr0, Wl1, Wr1, Wl2, Wr2);
    }
}

// ---------------- CSR build ----------------
__global__ void k_zero() {
    int i = blockIdx.x*blockDim.x + threadIdx.x;
    if (i < NN) g_deg[i] = 0;
    if (i < 64) g_bsum[i] = 0;
}
__global__ void k_hist(const int* __restrict__ ei) {
    int e = blockIdx.x*blockDim.x + threadIdx.x;
    if (e < NE) atomicAdd(&g_deg[ei[NE + e]], 1);
}
__global__ void k_scan1() {
    __shared__ int ws[32];
    int tid = threadIdx.x, lane = tid & 31, w = tid >> 5;
    int gid = blockIdx.x*1024 + tid;
    int s = (gid < NN) ? g_deg[gid] : 0;
    #pragma unroll
    for (int o = 1; o < 32; o <<= 1) {
        int t = __shfl_up_sync(0xffffffffu, s, o);
        if (lane >= o) s += t;
    }
    if (lane == 31) ws[w] = s;
    __syncthreads();
    if (w == 0) {
        int x = ws[lane];
        #pragma unroll
        for (int o = 1; o < 32; o <<= 1) {
            int t = __shfl_up_sync(0xffffffffu, x, o);
            if (lane >= o) x += t;
        }
        ws[lane] = x;
    }
    __syncthreads();
    if (w > 0) s += ws[w-1];
    if (gid < NN) g_off[gid+1] = s;
    if (tid == 1023) g_bsum[blockIdx.x] = s;
}
__global__ void k_scan2() {
    __shared__ int s[64];
    int tid = threadIdx.x;
    int v = g_bsum[tid];
    s[tid] = v; __syncthreads();
    for (int o = 1; o < 64; o <<= 1) {
        int t = (tid >= o) ? s[tid-o] : 0;
        __syncthreads(); s[tid] += t; __syncthreads();
    }
    g_bsum[tid] = s[tid] - v;
}
__global__ void k_scan3() {
    int gid = blockIdx.x*1024 + threadIdx.x;
    if (gid >= NN) return;
    int incl = g_off[gid+1] + g_bsum[blockIdx.x];
    g_off[gid+1] = incl;
    g_pos[gid]   = incl - g_deg[gid];
    if (gid == 0) g_off[0] = 0;
}
__global__ void k_fill(const int* __restrict__ ei) {
    int e = blockIdx.x*blockDim.x + threadIdx.x;
    if (e < NE) {
        int dst = ei[NE + e];
        int p = atomicAdd(&g_pos[dst], 1);
        g_csr[p] = ei[e];
    }
}

// ---------------- 2-term fp16 GEMM: A*(Bh+Bl), 96KB smem, 2 CTA/SM ----------------
// smem: A fp16 [0,32K), Bh [32K,64K), Bl [64K,96K). No mid-kernel syncs.
// !SPLIT47: g==0 -> out0 packed fp16x2 (stride 64 u32); g==1 -> out1 fp32 (stride 128)
// SPLIT47:  cols 0-63 -> out0 fp32 (stride DO), 64-127 -> out1 (stride DO)
template<bool SPLIT47>
__global__ void __launch_bounds__(256, 2) k_gemm_mma(
    const float* __restrict__ X0, const float* __restrict__ X1, int NSPLIT,
    const uint8_t* __restrict__ imgHi, const uint8_t* __restrict__ imgLo,
    void* __restrict__ out0, float* __restrict__ out1, int M)
{
    extern __shared__ char smem[];
    const int tid = threadIdx.x;
    const int bm = blockIdx.x * 128;
    const int g  = blockIdx.y;
    uint32_t sb = smem_u32(smem);

    // A fill: fp32 -> fp16, chunk-swizzled, 256B rows
    #pragma unroll
    for (int i = 0; i < 8; i++) {
        int id = tid + i*256;
        int row = id >> 4, c8 = id & 15;
        int gm = bm + row;
        uint32_t hp[4];
        if (gm < M) {
            const float* src = (gm < NSPLIT) ? (X0 + (size_t)gm*128)
                                             : (X1 + (size_t)(gm - NSPLIT)*128);
            float4 f0 = *(const float4*)(src + c8*8);
            float4 f1 = *(const float4*)(src + c8*8 + 4);
            hp[0] = pack_h2(f0.x, f0.y); hp[1] = pack_h2(f0.z, f0.w);
            hp[2] = pack_h2(f1.x, f1.y); hp[3] = pack_h2(f1.z, f1.w);
        } else {
            hp[0] = hp[1] = hp[2] = hp[3] = 0u;
        }
        uint32_t off = (uint32_t)row*256u + (uint32_t)((c8 ^ (row & 7)) << 4);
        *(uint4*)(smem + off) = make_uint4(hp[0], hp[1], hp[2], hp[3]);
    }
    // B copy: 32KB hi + 32KB lo slice, fully resident
    {
        const uint4* bh = (const uint4*)(imgHi + (size_t)g*32768);
        const uint4* bl = (const uint4*)(imgLo + (size_t)g*32768);
        #pragma unroll
        for (int i = 0; i < 8; i++) {
            int id = tid + i*256;
            ((uint4*)(smem + 32768))[id] = bh[id];
            ((uint4*)(smem + 65536))[id] = bl[id];
        }
    }
    __syncthreads();

    const int lane = tid & 31, w = tid >> 5;
    const int tm = (w >> 1) * 32, tn = (w & 1) * 64;
    const int lrow = lane & 15;
    const uint32_t lsel = (uint32_t)(lane >> 4);

    float acc[2][8][4];
    #pragma unroll
    for (int a = 0; a < 2; a++)
        #pragma unroll
        for (int b = 0; b < 8; b++)
            #pragma unroll
            for (int c = 0; c < 4; c++) acc[a][b][c] = 0.f;

    #pragma unroll
    for (int k16 = 0; k16 < 8; k16++) {
        const uint32_t c8 = (uint32_t)(k16*2) + lsel;
        // A fragments: loaded once, used by both terms
        uint32_t a[2][4];
        #pragma unroll
        for (int mt = 0; mt < 2; mt++) {
            int row = tm + mt*16 + lrow;
            ldsm4(a[mt], sb + (uint32_t)row*256u + ((c8 ^ (uint32_t)(row & 7)) << 4));
        }
        #pragma unroll
        for (int term = 0; term < 2; term++) {
            uint32_t bbase = sb + 32768u + (uint32_t)term*32768u;
            uint32_t b[4][4];
            #pragma unroll
            for (int bt = 0; bt < 4; bt++) {
                int n = tn + bt*16 + lrow;
                ldsm4(b[bt], bbase + (uint32_t)n*256u + ((c8 ^ (uint32_t)(n & 7)) << 4));
            }
            #pragma unroll
            for (int mt = 0; mt < 2; mt++)
                #pragma unroll
                for (int bt = 0; bt < 4; bt++) {
                    mma16816(acc[mt][bt*2+0], a[mt], b[bt][0], b[bt][2]);
                    mma16816(acc[mt][bt*2+1], a[mt], b[bt][1], b[bt][3]);
                }
        }
    }

    if constexpr (!SPLIT47) {
        if (g == 0) {   // t: packed fp16x2
            uint32_t* dst = (uint32_t*)out0;
            #pragma unroll
            for (int mt = 0; mt < 2; mt++) {
                int r0 = bm + tm + mt*16 + (lane >> 2);
                int r1 = r0 + 8;
                #pragma unroll
                for (int nt = 0; nt < 8; nt++) {
                    int cp = (tn + nt*8 + (lane & 3)*2) >> 1;
                    if (r0 < M) dst[(size_t)r0*64 + cp] = pack_h2(acc[mt][nt][0], acc[mt][nt][1]);
                    if (r1 < M) dst[(size_t)r1*64 + cp] = pack_h2(acc[mt][nt][2], acc[mt][nt][3]);
                }
            }
        } else {        // r: fp32
            #pragma unroll
            for (int mt = 0; mt < 2; mt++) {
                int r0 = bm + tm + mt*16 + (lane >> 2);
                int r1 = r0 + 8;
                #pragma unroll
                for (int nt = 0; nt < 8; nt++) {
                    int col = tn + nt*8 + (lane & 3)*2;
                    if (r0 < M) *(float2*)(out1 + (size_t)r0*128 + col)
                        = make_float2(acc[mt][nt][0], acc[mt][nt][1]);
                    if (r1 < M) *(float2*)(out1 + (size_t)r1*128 + col)
                        = make_float2(acc[mt][nt][2], acc[mt][nt][3]);
                }
            }
        }
    } else {
        float* dst = (w & 1) ? out1 : (float*)out0;
        #pragma unroll
        for (int mt = 0; mt < 2; mt++) {
            int r0 = bm + tm + mt*16 + (lane >> 2);
            int r1 = r0 + 8;
            #pragma unroll
            for (int nt = 0; nt < 8; nt++) {
                int cl = nt*8 + (lane & 3)*2;
                if (cl < DO) {
                    if (r0 < M) dst[(size_t)r0*DO + cl] = acc[mt][nt][0];
                    if (r1 < M) dst[(size_t)r1*DO + cl] = acc[mt][nt][2];
                }
                if (cl + 1 < DO) {
                    if (r0 < M) dst[(size_t)r0*DO + cl + 1] = acc[mt][nt][1];
                    if (r1 < M) dst[(size_t)r1*DO + cl + 1] = acc[mt][nt][3];
                }
            }
        }
    }
}

// ---------------- 128-dim mean-agg (fp16 t, MLP-4) + bias + self + relu ----------------
__global__ void k_agg128(const uint32_t* __restrict__ t, const float* __restrict__ r,
                         const float* __restrict__ bias,
                         float* __restrict__ hout, float* __restrict__ dout)
{
    int w = (blockIdx.x*blockDim.x + threadIdx.x) >> 5;
    int lane = threadIdx.x & 31;
    if (w >= MM) return;
    int b = (w >= NN);
    int i = w - b*NN;
    int base = b*NN;
    int e0 = g_off[i], e1 = g_off[i+1];
    float4 acc0 = make_float4(0.f,0.f,0.f,0.f);
    float4 acc1 = make_float4(0.f,0.f,0.f,0.f);
    int e = e0;
    for (; e + 4 <= e1; e += 4) {
        int j0 = g_csr[e], j1 = g_csr[e+1], j2 = g_csr[e+2], j3 = g_csr[e+3];
        uint2 u0 = *(const uint2*)(t + ((size_t)(base + j0) << 6) + (lane << 1));
        uint2 u1 = *(const uint2*)(t + ((size_t)(base + j1) << 6) + (lane << 1));
        uint2 u2 = *(const uint2*)(t + ((size_t)(base + j2) << 6) + (lane << 1));
        uint2 u3 = *(const uint2*)(t + ((size_t)(base + j3) << 6) + (lane << 1));
        float2 a0 = __half22float2(*(__half2*)&u0.x), b0 = __half22float2(*(__half2*)&u0.y);
        float2 a1 = __half22float2(*(__half2*)&u1.x), b1 = __half22float2(*(__half2*)&u1.y);
        float2 a2 = __half22float2(*(__half2*)&u2.x), b2 = __half22float2(*(__half2*)&u2.y);
        float2 a3 = __half22float2(*(__half2*)&u3.x), b3 = __half22float2(*(__half2*)&u3.y);
        acc0.x += a0.x + a1.x; acc0.y += a0.y + a1.y;
        acc0.z += b0.x + b1.x; acc0.w += b0.y + b1.y;
        acc1.x += a2.x + a3.x; acc1.y += a2.y + a3.y;
        acc1.z += b2.x + b3.x; acc1.w += b2.y + b3.y;
    }
    for (; e < e1; e++) {
        int j = g_csr[e];
        uint2 u = *(const uint2*)(t + ((size_t)(base + j) << 6) + (lane << 1));
        float2 a = __half22float2(*(__half2*)&u.x), bb = __half22float2(*(__half2*)&u.y);
        acc0.x += a.x; acc0.y += a.y; acc0.z += bb.x; acc0.w += bb.y;
    }
    float4 acc = make_float4(acc0.x + acc1.x, acc0.y + acc1.y,
                             acc0.z + acc1.z, acc0.w + acc1.w);
    float inv = (e1 > e0) ? 1.f/(float)(e1 - e0) : 0.f;
    float4 bb = *(const float4*)(bias + (lane << 2));
    float4 rr = *(const float4*)(r + ((size_t)w << 7) + (lane << 2));
    float4 o;
    o.x = fmaxf(fmaf(acc.x, inv, bb.x + rr.x), 0.f);
    o.y = fmaxf(fmaf(acc.y, inv, bb.y + rr.y), 0.f);
    o.z = fmaxf(fmaf(acc.z, inv, bb.z + rr.z), 0.f);
    o.w = fmaxf(fmaf(acc.w, inv, bb.w + rr.w), 0.f);
    if (hout) *(float4*)(hout + ((size_t)w << 7) + (lane << 2)) = o;
    if (dout) *(float4*)(dout + (size_t)b*OPB + (size_t)i*DH + (lane << 2)) = o;
}

// ---------------- 47-dim agg (fp32, MLP-2) + log_softmax ----------------
__global__ void k_agg47(const float* __restrict__ t2, const float* __restrict__ r2,
                        const float* __restrict__ bias, float* __restrict__ dout)
{
    int w = (blockIdx.x*blockDim.x + threadIdx.x) >> 5;
    int lane = threadIdx.x & 31;
    if (w >= MM) return;
    int b = (w >= NN);
    int i = w - b*NN;
    int base = b*NN;
    int f0 = lane*2, f1 = lane*2 + 1;
    bool v0 = (f0 < DO), v1 = (f1 < DO);
    int e0 = g_off[i], e1 = g_off[i+1];
    float a0 = 0.f, a1 = 0.f, c0 = 0.f, c1 = 0.f;
    int e = e0;
    for (; e + 2 <= e1; e += 2) {
        const float* rowA = t2 + (size_t)(base + g_csr[e])   * DO;
        const float* rowB = t2 + (size_t)(base + g_csr[e+1]) * DO;
        if (v0) { a0 += rowA[f0]; c0 += rowB[f0]; }
        if (v1) { a1 += rowA[f1]; c1 += rowB[f1]; }
    }
    for (; e < e1; e++) {
        const float* row = t2 + (size_t)(base + g_csr[e]) * DO;
        if (v0) a0 += row[f0];
        if (v1) a1 += row[f1];
    }
    a0 += c0; a1 += c1;
    float inv = (e1 > e0) ? 1.f/(float)(e1 - e0) : 0.f;
    float z0 = v0 ? fmaf(a0, inv, bias[f0] + r2[(size_t)w*DO + f0]) : -INFINITY;
    float z1 = v1 ? fmaf(a1, inv, bias[f1] + r2[(size_t)w*DO + f1]) : -INFINITY;
    float m = fmaxf(z0, z1);
    #pragma unroll
    for (int o = 16; o; o >>= 1) m = fmaxf(m, __shfl_xor_sync(0xffffffffu, m, o));
    float s = (v0 ? expf(z0 - m) : 0.f) + (v1 ? expf(z1 - m) : 0.f);
    #pragma unroll
    for (int o = 16; o; o >>= 1) s += __shfl_xor_sync(0xffffffffu, s, o);
    float lse = m + logf(s);
    float* ybase = dout + (size_t)b*OPB + (size_t)NN*DH        + (size_t)i*DO;
    float* zbase = dout + (size_t)b*OPB + (size_t)NN*(DH + DO) + (size_t)i*DO;
    if (v0) { zbase[f0] = z0; ybase[f0] = z0 - lse; }
    if (v1) { zbase[f1] = z1; ybase[f1] = z1 - lse; }
}

// ---------------- orchestration ----------------
extern "C" void kernel_launch(void* const* d_in, const int* in_sizes, int n_in,
                              void* d_out, int out_size)
{
    const float* x     = (const float*)d_in[0];
    const int*   ei    = (const int*)  d_in[1];
    const float* noise = (const float*)d_in[2];
    const float* Wl0   = (const float*)d_in[3];
    const float* bl0   = (const float*)d_in[4];
    const float* Wr0   = (const float*)d_in[5];
    const float* Wl1   = (const float*)d_in[6];
    const float* bl1   = (const float*)d_in[7];
    const float* Wr1   = (const float*)d_in[8];
    const float* Wl2   = (const float*)d_in[9];
    const float* bl2   = (const float*)d_in[10];
    const float* Wr2   = (const float*)d_in[11];
    float* out = (float*)d_out;

    float *px2, *pt, *pr, *ph, *pt2, *pr2;
    uint8_t* pw;
    cudaGetSymbolAddress((void**)&px2, g_x2);
    cudaGetSymbolAddress((void**)&pt,  g_t);
    cudaGetSymbolAddress((void**)&pr,  g_r);
    cudaGetSymbolAddress((void**)&ph,  g_h);
    cudaGetSymbolAddress((void**)&pt2, g_t2);
    cudaGetSymbolAddress((void**)&pr2, g_r2);
    cudaGetSymbolAddress((void**)&pw,  g_wimg);

    const int SM = 98304;   // 96KB -> 2 CTAs/SM
    cudaFuncSetAttribute(k_gemm_mma<false>, cudaFuncAttributeMaxDynamicSharedMemorySize, SM);
    cudaFuncSetAttribute(k_gemm_mma<true>,  cudaFuncAttributeMaxDynamicSharedMemorySize, SM);

    int gBlocks = (MM + 127)/128;
    dim3 gBig(gBlocks, 2);
    dim3 gSml(gBlocks, 1);
    int aggBlocks = (MM*32 + 255)/256;

    // idx 0: noise + weight conversion
    k_prep<<<NOISE_BLOCKS + 40, 256>>>(x, noise, Wl0, Wr0, Wl1, Wr1, Wl2, Wr2);
    // idx 1-2
    k_zero <<<(NN + 255)/256, 256>>>();
    k_hist <<<(NE + 255)/256, 256>>>(ei);
    // idx 3: layer-0 GEMM (ncu capture target)
    k_gemm_mma<false><<<gBig, 256, SM>>>(px2, px2, MM, pw, pw + 65536, pt, pr, MM);
    // idx 4-7: finish CSR
    k_scan1<<<NB_SCAN, 1024>>>();
    k_scan2<<<1, 64>>>();
    k_scan3<<<NB_SCAN, 1024>>>();
    k_fill <<<(NE + 255)/256, 256>>>(ei);
    // layer 0 agg -> h1
    k_agg128<<<aggBlocks, 256>>>((const uint32_t*)pt, pr, bl0, ph, nullptr);
    // layer 1
    k_gemm_mma<false><<<gBig, 256, SM>>>(ph, ph, MM, pw + 131072, pw + 196608, pt, pr, MM);
    k_agg128<<<aggBlocks, 256>>>((const uint32_t*)pt, pr, bl1, nullptr, out);
    // layer 2 (reads h2 from d_out)
    k_gemm_mma<true><<<gSml, 256, SM>>>(out, out + OPB, NN,
                                        pw + 262144, pw + 294912, pt2, pr2, MM);
    k_agg47<<<aggBlocks, 256>>>(pt2, pr2, bl2, out);
}

// round 10
// speedup vs baseline: 1.6943x; 1.1404x over previous
#include <cuda_runtime.h>
#include <cuda_bf16.h>
#include <cuda_fp16.h>
#include <math.h>
#include <stdint.h>

#define NN 50000
#define NE 800000
#define DH 128
#define DO 47
#define MM (2*NN)
#define OPB (NN*(DH+DO+DO))
#define NB_SCAN ((NN + 1023)/1024)

// ---------------- scratch ----------------
__device__ float g_x2[MM*DH];
__device__ float g_t [MM*DH];     // t as fp16x2 (MM x 64 u32)
__device__ float g_r [MM*DH];
__device__ float g_h [MM*DH];     // reused as h1 fp16 image (100096 rows x 256B)
__device__ float g_t2[MM*DO];
__device__ float g_r2[MM*DO];
__device__ int   g_deg[NN];
__device__ int   g_off[NN+1];
__device__ int   g_pos[NN];
__device__ int   g_csr[NE];
__device__ int   g_bsum[64];
// fp16 weight images, [g-slice 32KB][n row 256B] chunk-swizzled
__device__ __align__(16) uint8_t g_wimg[2*65536 + 2*65536 + 2*32768];

// ---------------- helpers ----------------
__device__ __forceinline__ uint32_t smem_u32(const void* p) {
    uint32_t a;
    asm("{ .reg .u64 t; cvta.to.shared.u64 t, %1; cvt.u32.u64 %0, t; }" : "=r"(a) : "l"(p));
    return a;
}
__device__ __forceinline__ void ldsm4(uint32_t* r, uint32_t addr) {
    asm volatile("ldmatrix.sync.aligned.m8n8.x4.shared.b16 {%0,%1,%2,%3}, [%4];"
        : "=r"(r[0]), "=r"(r[1]), "=r"(r[2]), "=r"(r[3]) : "r"(addr));
}
__device__ __forceinline__ void mma16816(float* c, const uint32_t* a, uint32_t b0, uint32_t b1) {
    asm volatile("mma.sync.aligned.m16n8k16.row.col.f32.f16.f16.f32 "
        "{%0,%1,%2,%3}, {%4,%5,%6,%7}, {%8,%9}, {%0,%1,%2,%3};"
        : "+f"(c[0]), "+f"(c[1]), "+f"(c[2]), "+f"(c[3])
        : "r"(a[0]), "r"(a[1]), "r"(a[2]), "r"(a[3]), "r"(b0), "r"(b1));
}
__device__ __forceinline__ uint32_t pack_h2(float a, float b) {
    __half2 h = __floats2half2_rn(a, b);
    return *(uint32_t*)&h;
}
__device__ __forceinline__ void cvt_hilo16(const float* v, uint32_t* hp, uint32_t* lp) {
    #pragma unroll
    for (int p = 0; p < 4; p++) {
        __half2 h2 = __floats2half2_rn(v[2*p], v[2*p+1]);
        float l0 = v[2*p]   - __low2float(h2);
        float l1 = v[2*p+1] - __high2float(h2);
        __half2 l2 = __floats2half2_rn(l0, l1);
        hp[p] = *(uint32_t*)&h2;
        lp[p] = *(uint32_t*)&l2;
    }
}

// ---------------- weight image writer: [g 32KB][n][256B] ----------------
__device__ __forceinline__ void wconv_item(int id,
        const float* Wl0, const float* Wr0, const float* Wl1, const float* Wr1,
        const float* Wl2, const float* Wr2) {
    const float* src = nullptr;
    uint8_t *imgHi, *imgLo;
    int row, c8;
    if (id < 4096) {
        row = id >> 4; c8 = id & 15;
        imgHi = g_wimg;          imgLo = g_wimg + 65536;
        src = (row < 128) ? (Wl0 + (size_t)row*128) : (Wr0 + (size_t)(row-128)*128);
    } else if (id < 8192) {
        id -= 4096; row = id >> 4; c8 = id & 15;
        imgHi = g_wimg + 131072; imgLo = g_wimg + 196608;
        src = (row < 128) ? (Wl1 + (size_t)row*128) : (Wr1 + (size_t)(row-128)*128);
    } else if (id < 10240) {
        id -= 8192; row = id >> 4; c8 = id & 15;
        imgHi = g_wimg + 262144; imgLo = g_wimg + 294912;
        if (row < 47)                     src = Wl2 + (size_t)row*128;
        else if (row >= 64 && row < 111)  src = Wr2 + (size_t)(row-64)*128;
        else                              src = nullptr;
    } else return;
    float v[8];
    #pragma unroll
    for (int j = 0; j < 8; j++) v[j] = src ? src[c8*8 + j] : 0.f;
    uint32_t hp[4], lp[4];
    cvt_hilo16(v, hp, lp);
    int gsl = row >> 7, n = row & 127;
    uint32_t off = (uint32_t)gsl*32768u + (uint32_t)n*256u
                 + (uint32_t)((c8 ^ (n & 7)) << 4);
    *(uint4*)(imgHi + off) = make_uint4(hp[0], hp[1], hp[2], hp[3]);
    *(uint4*)(imgLo + off) = make_uint4(lp[0], lp[1], lp[2], lp[3]);
}

// ---------------- prep: noise + wconv fused ----------------
#define NOISE_BLOCKS (NN/8)
__global__ void k_prep(const float* __restrict__ x, const float* __restrict__ noise,
                       const float* Wl0, const float* Wr0,
                       const float* Wl1, const float* Wr1,
                       const float* Wl2, const float* Wr2) {
    if (blockIdx.x < NOISE_BLOCKS) {
        int w = (blockIdx.x*blockDim.x + threadIdx.x) >> 5;
        int lane = threadIdx.x & 31;
        const float4 nv = *(const float4*)(noise + (size_t)w*DH + lane*4);
        float ss = nv.x*nv.x + nv.y*nv.y + nv.z*nv.z + nv.w*nv.w;
        #pragma unroll
        for (int o = 16; o; o >>= 1) ss += __shfl_xor_sync(0xffffffffu, ss, o);
        float sc = 0.1f / fmaxf(sqrtf(ss), 1e-12f);
        float4 xv = *(const float4*)(x + (size_t)w*DH + lane*4);
        float4 xn;
        xn.x = xv.x + ((xv.x>0.f)?1.f:((xv.x<0.f)?-1.f:0.f)) * nv.x * sc;
        xn.y = xv.y + ((xv.y>0.f)?1.f:((xv.y<0.f)?-1.f:0.f)) * nv.y * sc;
        xn.z = xv.z + ((xv.z>0.f)?1.f:((xv.z<0.f)?-1.f:0.f)) * nv.z * sc;
        xn.w = xv.w + ((xv.w>0.f)?1.f:((xv.w<0.f)?-1.f:0.f)) * nv.w * sc;
        *(float4*)(g_x2 + (size_t)w*DH      + lane*4) = xv;
        *(float4*)(g_x2 + (size_t)(NN+w)*DH + lane*4) = xn;
    } else {
        int id = (blockIdx.x - NOISE_BLOCKS)*blockDim.x + threadIdx.x;
        wconv_item(id, Wl0, Wr0, Wl1, Wr1, Wl2, Wr2);
    }
}

// ---------------- CSR build ----------------
__global__ void k_zero() {
    int i = blockIdx.x*blockDim.x + threadIdx.x;
    if (i < NN) g_deg[i] = 0;
    if (i < 64) g_bsum[i] = 0;
}
__global__ void k_hist(const int* __restrict__ ei) {
    int e = blockIdx.x*blockDim.x + threadIdx.x;
    if (e < NE) atomicAdd(&g_deg[ei[NE + e]], 1);
}
__global__ void k_scan1() {
    __shared__ int ws[32];
    int tid = threadIdx.x, lane = tid & 31, w = tid >> 5;
    int gid = blockIdx.x*1024 + tid;
    int s = (gid < NN) ? g_deg[gid] : 0;
    #pragma unroll
    for (int o = 1; o < 32; o <<= 1) {
        int t = __shfl_up_sync(0xffffffffu, s, o);
        if (lane >= o) s += t;
    }
    if (lane == 31) ws[w] = s;
    __syncthreads();
    if (w == 0) {
        int x = ws[lane];
        #pragma unroll
        for (int o = 1; o < 32; o <<= 1) {
            int t = __shfl_up_sync(0xffffffffu, x, o);
            if (lane >= o) x += t;
        }
        ws[lane] = x;
    }
    __syncthreads();
    if (w > 0) s += ws[w-1];
    if (gid < NN) g_off[gid+1] = s;
    if (tid == 1023) g_bsum[blockIdx.x] = s;
}
__global__ void k_scan2() {
    __shared__ int s[64];
    int tid = threadIdx.x;
    int v = g_bsum[tid];
    s[tid] = v; __syncthreads();
    for (int o = 1; o < 64; o <<= 1) {
        int t = (tid >= o) ? s[tid-o] : 0;
        __syncthreads(); s[tid] += t; __syncthreads();
    }
    g_bsum[tid] = s[tid] - v;
}
__global__ void k_scan3() {
    int gid = blockIdx.x*1024 + threadIdx.x;
    if (gid >= NN) return;
    int incl = g_off[gid+1] + g_bsum[blockIdx.x];
    g_off[gid+1] = incl;
    g_pos[gid]   = incl - g_deg[gid];
    if (gid == 0) g_off[0] = 0;
}
__global__ void k_fill(const int* __restrict__ ei) {
    int e = blockIdx.x*blockDim.x + threadIdx.x;
    if (e < NE) {
        int dst = ei[NE + e];
        int p = atomicAdd(&g_pos[dst], 1);
        g_csr[p] = ei[e];
    }
}

// ---------------- 2-term fp16 GEMM: A*(Bh+Bl), 96KB smem, 2 CTA/SM ----------------
// smem: A fp16 [0,32K), Bh [32K,64K), Bl [64K,96K). No mid-kernel syncs.
// AIMG: A taken from pre-swizzled fp16 image (raw copy); else fp32 convert (X0/X1 split).
// !SPLIT47: g==0 -> out0 packed fp16x2 (stride 64 u32); g==1 -> out1 fp32 (stride 128)
// SPLIT47:  cols 0-63 -> out0 fp32 (stride DO), 64-127 -> out1 (stride DO)
template<bool SPLIT47, bool AIMG>
__global__ void __launch_bounds__(256, 2) k_gemm_mma(
    const float* __restrict__ X0, const float* __restrict__ X1, int NSPLIT,
    const uint8_t* __restrict__ Aimg,
    const uint8_t* __restrict__ imgHi, const uint8_t* __restrict__ imgLo,
    void* __restrict__ out0, float* __restrict__ out1, int M)
{
    extern __shared__ char smem[];
    const int tid = threadIdx.x;
    const int bm = blockIdx.x * 128;
    const int g  = blockIdx.y;
    uint32_t sb = smem_u32(smem);

    if constexpr (AIMG) {
        const uint4* src = (const uint4*)(Aimg + (size_t)bm*256);
        #pragma unroll
        for (int i = 0; i < 8; i++) {
            int id = tid + i*256;
            ((uint4*)smem)[id] = src[id];
        }
    } else {
        #pragma unroll
        for (int i = 0; i < 8; i++) {
            int id = tid + i*256;
            int row = id >> 4, c8 = id & 15;
            int gm = bm + row;
            uint32_t hp[4];
            if (gm < M) {
                const float* src = (gm < NSPLIT) ? (X0 + (size_t)gm*128)
                                                 : (X1 + (size_t)(gm - NSPLIT)*128);
                float4 f0 = *(const float4*)(src + c8*8);
                float4 f1 = *(const float4*)(src + c8*8 + 4);
                hp[0] = pack_h2(f0.x, f0.y); hp[1] = pack_h2(f0.z, f0.w);
                hp[2] = pack_h2(f1.x, f1.y); hp[3] = pack_h2(f1.z, f1.w);
            } else {
                hp[0] = hp[1] = hp[2] = hp[3] = 0u;
            }
            uint32_t off = (uint32_t)row*256u + (uint32_t)((c8 ^ (row & 7)) << 4);
            *(uint4*)(smem + off) = make_uint4(hp[0], hp[1], hp[2], hp[3]);
        }
    }
    {
        const uint4* bh = (const uint4*)(imgHi + (size_t)g*32768);
        const uint4* bl = (const uint4*)(imgLo + (size_t)g*32768);
        #pragma unroll
        for (int i = 0; i < 8; i++) {
            int id = tid + i*256;
            ((uint4*)(smem + 32768))[id] = bh[id];
            ((uint4*)(smem + 65536))[id] = bl[id];
        }
    }
    __syncthreads();

    const int lane = tid & 31, w = tid >> 5;
    const int tm = (w >> 1) * 32, tn = (w & 1) * 64;
    const int lrow = lane & 15;
    const uint32_t lsel = (uint32_t)(lane >> 4);

    float acc[2][8][4];
    #pragma unroll
    for (int a = 0; a < 2; a++)
        #pragma unroll
        for (int b = 0; b < 8; b++)
            #pragma unroll
            for (int c = 0; c < 4; c++) acc[a][b][c] = 0.f;

    #pragma unroll
    for (int k16 = 0; k16 < 8; k16++) {
        const uint32_t c8 = (uint32_t)(k16*2) + lsel;
        uint32_t a[2][4];
        #pragma unroll
        for (int mt = 0; mt < 2; mt++) {
            int row = tm + mt*16 + lrow;
            ldsm4(a[mt], sb + (uint32_t)row*256u + ((c8 ^ (uint32_t)(row & 7)) << 4));
        }
        #pragma unroll
        for (int term = 0; term < 2; term++) {
            uint32_t bbase = sb + 32768u + (uint32_t)term*32768u;
            uint32_t b[4][4];
            #pragma unroll
            for (int bt = 0; bt < 4; bt++) {
                int n = tn + bt*16 + lrow;
                ldsm4(b[bt], bbase + (uint32_t)n*256u + ((c8 ^ (uint32_t)(n & 7)) << 4));
            }
            #pragma unroll
            for (int mt = 0; mt < 2; mt++)
                #pragma unroll
                for (int bt = 0; bt < 4; bt++) {
                    mma16816(acc[mt][bt*2+0], a[mt], b[bt][0], b[bt][2]);
                    mma16816(acc[mt][bt*2+1], a[mt], b[bt][1], b[bt][3]);
                }
        }
    }

    if constexpr (!SPLIT47) {
        if (g == 0) {   // t: packed fp16x2
            uint32_t* dst = (uint32_t*)out0;
            #pragma unroll
            for (int mt = 0; mt < 2; mt++) {
                int r0 = bm + tm + mt*16 + (lane >> 2);
                int r1 = r0 + 8;
                #pragma unroll
                for (int nt = 0; nt < 8; nt++) {
                    int cp = (tn + nt*8 + (lane & 3)*2) >> 1;
                    if (r0 < M) dst[(size_t)r0*64 + cp] = pack_h2(acc[mt][nt][0], acc[mt][nt][1]);
                    if (r1 < M) dst[(size_t)r1*64 + cp] = pack_h2(acc[mt][nt][2], acc[mt][nt][3]);
                }
            }
        } else {        // r: fp32
            #pragma unroll
            for (int mt = 0; mt < 2; mt++) {
                int r0 = bm + tm + mt*16 + (lane >> 2);
                int r1 = r0 + 8;
                #pragma unroll
                for (int nt = 0; nt < 8; nt++) {
                    int col = tn + nt*8 + (lane & 3)*2;
                    if (r0 < M) *(float2*)(out1 + (size_t)r0*128 + col)
                        = make_float2(acc[mt][nt][0], acc[mt][nt][1]);
                    if (r1 < M) *(float2*)(out1 + (size_t)r1*128 + col)
                        = make_float2(acc[mt][nt][2], acc[mt][nt][3]);
                }
            }
        }
    } else {
        float* dst = (w & 1) ? out1 : (float*)out0;
        #pragma unroll
        for (int mt = 0; mt < 2; mt++) {
            int r0 = bm + tm + mt*16 + (lane >> 2);
            int r1 = r0 + 8;
            #pragma unroll
            for (int nt = 0; nt < 8; nt++) {
                int cl = nt*8 + (lane & 3)*2;
                if (cl < DO) {
                    if (r0 < M) dst[(size_t)r0*DO + cl] = acc[mt][nt][0];
                    if (r1 < M) dst[(size_t)r1*DO + cl] = acc[mt][nt][2];
                }
                if (cl + 1 < DO) {
                    if (r0 < M) dst[(size_t)r0*DO + cl + 1] = acc[mt][nt][1];
                    if (r1 < M) dst[(size_t)r1*DO + cl + 1] = acc[mt][nt][3];
                }
            }
        }
    }
}

// ---------------- branch-merged 128-dim mean-agg + bias + self + relu ----------------
// one warp per node, BOTH branches. himg: write swizzled fp16 image rows i and NN+i.
// dout: write fp32 to d_out both branch slots.
__global__ void k_agg128(const uint32_t* __restrict__ t, const float* __restrict__ r,
                         const float* __restrict__ bias,
                         uint32_t* __restrict__ himg, float* __restrict__ dout)
{
    int i = (blockIdx.x*blockDim.x + threadIdx.x) >> 5;
    int lane = threadIdx.x & 31;
    if (i >= NN) return;
    int e0 = g_off[i], e1 = g_off[i+1];
    float4 ac = make_float4(0.f,0.f,0.f,0.f);
    float4 an = make_float4(0.f,0.f,0.f,0.f);
    int e = e0;
    for (; e + 2 <= e1; e += 2) {
        int j0 = g_csr[e], j1 = g_csr[e+1];
        uint2 c0 = *(const uint2*)(t + ((size_t)j0        << 6) + (lane << 1));
        uint2 n0 = *(const uint2*)(t + ((size_t)(NN + j0) << 6) + (lane << 1));
        uint2 c1 = *(const uint2*)(t + ((size_t)j1        << 6) + (lane << 1));
        uint2 n1 = *(const uint2*)(t + ((size_t)(NN + j1) << 6) + (lane << 1));
        float2 cl0 = __half22float2(*(__half2*)&c0.x), ch0 = __half22float2(*(__half2*)&c0.y);
        float2 nl0 = __half22float2(*(__half2*)&n0.x), nh0 = __half22float2(*(__half2*)&n0.y);
        float2 cl1 = __half22float2(*(__half2*)&c1.x), ch1 = __half22float2(*(__half2*)&c1.y);
        float2 nl1 = __half22float2(*(__half2*)&n1.x), nh1 = __half22float2(*(__half2*)&n1.y);
        ac.x += cl0.x + cl1.x; ac.y += cl0.y + cl1.y;
        ac.z += ch0.x + ch1.x; ac.w += ch0.y + ch1.y;
        an.x += nl0.x + nl1.x; an.y += nl0.y + nl1.y;
        an.z += nh0.x + nh1.x; an.w += nh0.y + nh1.y;
    }
    if (e < e1) {
        int j = g_csr[e];
        uint2 c = *(const uint2*)(t + ((size_t)j        << 6) + (lane << 1));
        uint2 n = *(const uint2*)(t + ((size_t)(NN + j) << 6) + (lane << 1));
        float2 cl = __half22float2(*(__half2*)&c.x), ch = __half22float2(*(__half2*)&c.y);
        float2 nl = __half22float2(*(__half2*)&n.x), nh = __half22float2(*(__half2*)&n.y);
        ac.x += cl.x; ac.y += cl.y; ac.z += ch.x; ac.w += ch.y;
        an.x += nl.x; an.y += nl.y; an.z += nh.x; an.w += nh.y;
    }
    float inv = (e1 > e0) ? 1.f/(float)(e1 - e0) : 0.f;
    float4 bb = *(const float4*)(bias + (lane << 2));
    float4 rc = *(const float4*)(r + ((size_t)i        << 7) + (lane << 2));
    float4 rn = *(const float4*)(r + ((size_t)(NN + i) << 7) + (lane << 2));
    float4 oc, on;
    oc.x = fmaxf(fmaf(ac.x, inv, bb.x + rc.x), 0.f);
    oc.y = fmaxf(fmaf(ac.y, inv, bb.y + rc.y), 0.f);
    oc.z = fmaxf(fmaf(ac.z, inv, bb.z + rc.z), 0.f);
    oc.w = fmaxf(fmaf(ac.w, inv, bb.w + rc.w), 0.f);
    on.x = fmaxf(fmaf(an.x, inv, bb.x + rn.x), 0.f);
    on.y = fmaxf(fmaf(an.y, inv, bb.y + rn.y), 0.f);
    on.z = fmaxf(fmaf(an.z, inv, bb.z + rn.z), 0.f);
    on.w = fmaxf(fmaf(an.w, inv, bb.w + rn.w), 0.f);
    if (himg) {
        // image row = node row; lane owns bytes [lane*8, lane*8+8) -> chunk c8=lane>>1
        int c8 = lane >> 1, half = (lane & 1) << 3;
        uint32_t offc = (uint32_t)i*64u        + (((uint32_t)(c8 ^ (i        & 7)) << 4) + half)/4u;
        uint32_t offn = (uint32_t)(NN+i)*64u   + (((uint32_t)(c8 ^ ((NN+i)   & 7)) << 4) + half)/4u;
        *(uint2*)(himg + offc) = make_uint2(pack_h2(oc.x, oc.y), pack_h2(oc.z, oc.w));
        *(uint2*)(himg + offn) = make_uint2(pack_h2(on.x, on.y), pack_h2(on.z, on.w));
    }
    if (dout) {
        *(float4*)(dout + (size_t)i*DH + (lane << 2)) = oc;
        *(float4*)(dout + (size_t)OPB + (size_t)i*DH + (lane << 2)) = on;
    }
}

// ---------------- branch-merged 47-dim agg + log_softmax ----------------
__global__ void k_agg47(const float* __restrict__ t2, const float* __restrict__ r2,
                        const float* __restrict__ bias, float* __restrict__ dout)
{
    int i = (blockIdx.x*blockDim.x + threadIdx.x) >> 5;
    int lane = threadIdx.x & 31;
    if (i >= NN) return;
    int f0 = lane*2, f1 = lane*2 + 1;
    bool v0 = (f0 < DO), v1 = (f1 < DO);
    int e0 = g_off[i], e1 = g_off[i+1];
    float ac0 = 0.f, ac1 = 0.f, an0 = 0.f, an1 = 0.f;
    for (int e = e0; e < e1; e++) {
        int j = g_csr[e];
        const float* rowC = t2 + (size_t)j        * DO;
        const float* rowN = t2 + (size_t)(NN + j) * DO;
        if (v0) { ac0 += rowC[f0]; an0 += rowN[f0]; }
        if (v1) { ac1 += rowC[f1]; an1 += rowN[f1]; }
    }
    float inv = (e1 > e0) ? 1.f/(float)(e1 - e0) : 0.f;
    float b0 = v0 ? bias[f0] : 0.f;
    float b1 = v1 ? bias[f1] : 0.f;
    // branch 0 (clean)
    float zc0 = v0 ? fmaf(ac0, inv, b0 + r2[(size_t)i*DO + f0]) : -INFINITY;
    float zc1 = v1 ? fmaf(ac1, inv, b1 + r2[(size_t)i*DO + f1]) : -INFINITY;
    // branch 1 (noisy)
    float zn0 = v0 ? fmaf(an0, inv, b0 + r2[(size_t)(NN+i)*DO + f0]) : -INFINITY;
    float zn1 = v1 ? fmaf(an1, inv, b1 + r2[(size_t)(NN+i)*DO + f1]) : -INFINITY;
    float mc = fmaxf(zc0, zc1), mn = fmaxf(zn0, zn1);
    #pragma unroll
    for (int o = 16; o; o >>= 1) {
        mc = fmaxf(mc, __shfl_xor_sync(0xffffffffu, mc, o));
        mn = fmaxf(mn, __shfl_xor_sync(0xffffffffu, mn, o));
    }
    float sc = (v0 ? expf(zc0 - mc) : 0.f) + (v1 ? expf(zc1 - mc) : 0.f);
    float sn = (v0 ? expf(zn0 - mn) : 0.f) + (v1 ? expf(zn1 - mn) : 0.f);
    #pragma unroll
    for (int o = 16; o; o >>= 1) {
        sc += __shfl_xor_sync(0xffffffffu, sc, o);
        sn += __shfl_xor_sync(0xffffffffu, sn, o);
    }
    float lc = mc + logf(sc), ln = mn + logf(sn);
    float* ycb = dout + (size_t)NN*DH                       + (size_t)i*DO;
    float* zcb = dout + (size_t)NN*(DH + DO)                + (size_t)i*DO;
    float* ynb = dout + (size_t)OPB + (size_t)NN*DH         + (size_t)i*DO;
    float* znb = dout + (size_t)OPB + (size_t)NN*(DH + DO)  + (size_t)i*DO;
    if (v0) { zcb[f0] = zc0; ycb[f0] = zc0 - lc; znb[f0] = zn0; ynb[f0] = zn0 - ln; }
    if (v1) { zcb[f1] = zc1; ycb[f1] = zc1 - lc; znb[f1] = zn1; ynb[f1] = zn1 - ln; }
}

// ---------------- orchestration ----------------
extern "C" void kernel_launch(void* const* d_in, const int* in_sizes, int n_in,
                              void* d_out, int out_size)
{
    const float* x     = (const float*)d_in[0];
    const int*   ei    = (const int*)  d_in[1];
    const float* noise = (const float*)d_in[2];
    const float* Wl0   = (const float*)d_in[3];
    const float* bl0   = (const float*)d_in[4];
    const float* Wr0   = (const float*)d_in[5];
    const float* Wl1   = (const float*)d_in[6];
    const float* bl1   = (const float*)d_in[7];
    const float* Wr1   = (const float*)d_in[8];
    const float* Wl2   = (const float*)d_in[9];
    const float* bl2   = (const float*)d_in[10];
    const float* Wr2   = (const float*)d_in[11];
    float* out = (float*)d_out;

    float *px2, *pt, *pr, *ph, *pt2, *pr2;
    uint8_t* pw;
    cudaGetSymbolAddress((void**)&px2, g_x2);
    cudaGetSymbolAddress((void**)&pt,  g_t);
    cudaGetSymbolAddress((void**)&pr,  g_r);
    cudaGetSymbolAddress((void**)&ph,  g_h);
    cudaGetSymbolAddress((void**)&pt2, g_t2);
    cudaGetSymbolAddress((void**)&pr2, g_r2);
    cudaGetSymbolAddress((void**)&pw,  g_wimg);

    const int SM = 98304;   // 96KB -> 2 CTAs/SM
    cudaFuncSetAttribute((const void*)k_gemm_mma<false,false>, cudaFuncAttributeMaxDynamicSharedMemorySize, SM);
    cudaFuncSetAttribute((const void*)k_gemm_mma<false,true>,  cudaFuncAttributeMaxDynamicSharedMemorySize, SM);
    cudaFuncSetAttribute((const void*)k_gemm_mma<true,false>,  cudaFuncAttributeMaxDynamicSharedMemorySize, SM);

    int gBlocks = (MM + 127)/128;
    dim3 gBig(gBlocks, 2);
    dim3 gSml(gBlocks, 1);
    int aggBlocks = (NN*32 + 255)/256;   // warp per node (both branches)

    // idx 0: noise + weight conversion
    k_prep<<<NOISE_BLOCKS + 40, 256>>>(x, noise, Wl0, Wr0, Wl1, Wr1, Wl2, Wr2);
    // idx 1-2
    k_zero <<<(NN + 255)/256, 256>>>();
    k_hist <<<(NE + 255)/256, 256>>>(ei);
    // idx 3: layer-0 GEMM (ncu capture target)
    k_gemm_mma<false,false><<<gBig, 256, SM>>>(px2, px2, MM, nullptr,
                                               pw, pw + 65536, pt, pr, MM);
    // idx 4-7: finish CSR
    k_scan1<<<NB_SCAN, 1024>>>();
    k_scan2<<<1, 64>>>();
    k_scan3<<<NB_SCAN, 1024>>>();
    k_fill <<<(NE + 255)/256, 256>>>(ei);
    // layer 0 agg -> h1 fp16 image
    k_agg128<<<aggBlocks, 256>>>((const uint32_t*)pt, pr, bl0, (uint32_t*)ph, nullptr);
    // layer 1 (A from fp16 image)
    k_gemm_mma<false,true><<<gBig, 256, SM>>>(nullptr, nullptr, 0, (const uint8_t*)ph,
                                              pw + 131072, pw + 196608, pt, pr, MM);
    k_agg128<<<aggBlocks, 256>>>((const uint32_t*)pt, pr, bl1, nullptr, out);
    // layer 2 (reads h2 from d_out fp32)
    k_gemm_mma<true,false><<<gSml, 256, SM>>>(out, out + OPB, NN, nullptr,
                                              pw + 262144, pw + 294912, pt2, pr2, MM);
    k_agg47<<<aggBlocks, 256>>>(pt2, pr2, bl2, out);
}